// round 12
// baseline (speedup 1.0000x reference)
#include <cuda_runtime.h>
#include <cuda_bf16.h>
#include <cuda_fp16.h>
#include <cstdint>
#include <cstddef>

using bf16 = __nv_bfloat16;

constexpr int BATCH = 16;
constexpr int C     = 256;
constexpr int NP    = 2048;
constexpr int CQ    = 64;
constexpr float EPSBN = 1e-3f;

// ---------------- scratch (static device buffers; no allocation) -------------
__device__ float  g_h0[BATCH * C * NP];
__device__ float  g_h1[BATCH * C * NP];
__device__ __half g_energy[(size_t)BATCH * NP * NP];            // 134 MB
__device__ bf16   g_P     [(size_t)BATCH * NP * NP];            // 134 MB
__device__ bf16   g_xB [(size_t)BATCH * 2 * C * NP];            // [hi;lo]
__device__ bf16   g_hB0[(size_t)BATCH * 2 * C * NP];
__device__ bf16   g_hB1[(size_t)BATCH * 2 * C * NP];
__device__ bf16   g_q  [(size_t)BATCH * 2 * CQ * NP];           // [hi;lo]
__device__ bf16   g_xv [(size_t)BATCH * C * NP];                // plain bf16
__device__ bf16   g_uB [(size_t)BATCH * 2 * C * NP];
__device__ float  g_d  [BATCH * NP];
__device__ float  g_bnp[12 * C];
// weight splits [hi(256)|lo(256)]: rows: conv1 0..255, conv2 256..511, qk 512..767,
// v 768..1791, t 1792..2815
__device__ bf16   g_wA [(size_t)2816 * 512];

// ---------------- BN prefold -------------------------------------------------
__global__ void bn_prep(const float* g1, const float* b1, const float* m1, const float* v1,
                        const float* g2, const float* b2, const float* m2, const float* v2,
                        const float* sg, const float* sb, const float* sm, const float* sv,
                        const float* stb)
{
    int c = threadIdx.x;
    int w = blockIdx.x;
    if (w == 0) {
        float a = g1[c] * rsqrtf(v1[c] + EPSBN);
        g_bnp[c] = a; g_bnp[C + c] = b1[c] - m1[c] * a;
    } else if (w == 1) {
        float a = g2[c] * rsqrtf(v2[c] + EPSBN);
        g_bnp[2*C + c] = a; g_bnp[3*C + c] = b2[c] - m2[c] * a;
    } else {
        int i = w - 2;
        float a = sg[i*C + c] * rsqrtf(sv[i*C + c] + EPSBN);
        g_bnp[(4+i)*C + c] = a;
        g_bnp[(8+i)*C + c] = sb[i*C + c] - sm[i*C + c] * a + a * stb[i*C + c];
    }
}

// ---------------- split helpers ---------------------------------------------
__device__ __forceinline__ void split2(float v, bf16& hi, bf16& lo)
{
    hi = __float2bfloat16(v);
    lo = __float2bfloat16(v - __bfloat162float(hi));
}

// ALL weights in one launch: rows 0..255 conv1, 256..511 conv2, 512..767 qk,
// 768..1791 v, 1792..2815 t.  (Single launch also shifts the ncu -s 5 capture
// point onto a real GEMM.)
__global__ void wsplit_all(const float* __restrict__ c1, const float* __restrict__ c2,
                           const float* __restrict__ qk, const float* __restrict__ vw,
                           const float* __restrict__ tw)
{
    int idx = blockIdx.x * 256 + threadIdx.x;   // 0 .. 2816*256-1
    int row = idx >> 8, k = idx & 255;
    const float* src;
    int r;
    if (row < 256)       { src = c1; r = row; }
    else if (row < 512)  { src = c2; r = row - 256; }
    else if (row < 768)  { src = qk; r = row - 512; }
    else if (row < 1792) { src = vw; r = row - 768; }
    else                 { src = tw; r = row - 1792; }
    bf16 hi, lo; split2(src[r * 256 + k], hi, lo);
    bf16* d = g_wA + (size_t)row * 512;
    d[k] = hi; d[256 + k] = lo;
}

// x: src fp32 [B,C,NP] -> dst bf16 [B,2C,NP] = [hi;lo]
__global__ void xsplitB(const float* __restrict__ src, bf16* __restrict__ dst)
{
    size_t idx = (size_t)blockIdx.x * 256 + threadIdx.x;
    int b = (int)(idx / ((size_t)C * NP));
    size_t rem = idx - (size_t)b * C * NP;
    bf16 hi, lo; split2(src[idx], hi, lo);
    bf16* d = dst + (size_t)b * 2 * C * NP;
    d[rem] = hi; d[(size_t)C * NP + rem] = lo;
}

// ---------------- mma.sync bf16 GEMM with fused epilogues --------------------
enum { M_CONV1 = 0, M_CONV2, M_Q, M_ENERGY, M_XV, M_XR, M_TOUT };

__device__ __forceinline__ void ldm_x4(uint32_t* r, uint32_t a)
{
    asm volatile("ldmatrix.sync.aligned.m8n8.x4.shared.b16 {%0,%1,%2,%3}, [%4];"
                 : "=r"(r[0]), "=r"(r[1]), "=r"(r[2]), "=r"(r[3]) : "r"(a));
}
__device__ __forceinline__ void ldm_x4_t(uint32_t* r, uint32_t a)
{
    asm volatile("ldmatrix.sync.aligned.m8n8.x4.trans.shared.b16 {%0,%1,%2,%3}, [%4];"
                 : "=r"(r[0]), "=r"(r[1]), "=r"(r[2]), "=r"(r[3]) : "r"(a));
}
__device__ __forceinline__ void cpa16(uint32_t s, const void* g)
{
    asm volatile("cp.async.cg.shared.global [%0], [%1], 16;" :: "r"(s), "l"(g));
}
__device__ __forceinline__ void mma_bf16(float* c, const uint32_t* a, const uint32_t* b)
{
    asm volatile("mma.sync.aligned.m16n8k16.row.col.f32.bf16.bf16.f32 "
                 "{%0,%1,%2,%3}, {%4,%5,%6,%7}, {%8,%9}, {%0,%1,%2,%3};"
                 : "+f"(c[0]), "+f"(c[1]), "+f"(c[2]), "+f"(c[3])
                 : "r"(a[0]), "r"(a[1]), "r"(a[2]), "r"(a[3]), "r"(b[0]), "r"(b[1]));
}

// MAPA: A logical k-thirds [hi|lo|hi] stored [hi|lo]  (phys K = 2*K3/3)
// MAPB: B logical k-thirds [hi;hi;lo] stored [hi;lo]
// SYM:  symmetric NxN product (energy); off-diagonal tiles mirrored via smem.
// BK=64 (R10 win) + 3-stage pipeline with wait_group 1 (R11).
template<int M, int N, int K3, int BM, int BN, bool ATRANS, int MODE,
         bool MAPA, bool MAPB, bool SYM = false>
__global__ void __launch_bounds__(256, 2)
gemm_bf16(const bf16* __restrict__ A, size_t sA,
          const bf16* __restrict__ B, size_t sB,
          float* __restrict__ Cp, size_t sC,
          const float* __restrict__ e1, const float* __restrict__ e2,
          const float* __restrict__ e3, float* __restrict__ out2,
          bf16* __restrict__ sp1, size_t sSp1)
{
    constexpr int BK = 64;
    constexpr int KB = K3 / BK;
    constexpr int T3 = K3 / 3;
    constexpr int WM = BM / 2, WN = BN / 4;
    constexpr int MT = WM / 16, NT = WN / 8;
    constexpr int A_STAGE = BM * BK * 2;      // bytes
    constexpr int B_STAGE = BK * BN * 2;
    constexpr int STAGE   = A_STAGE + B_STAGE;
    constexpr int CPRA = BK / 8;              // 16B chunks per A row (non-trans)
    constexpr int LDA = ATRANS ? M : (MAPA ? 2 * T3 : K3);

    extern __shared__ __align__(16) uint8_t smem[];
    const uint32_t s0 = (uint32_t)__cvta_generic_to_shared(smem);

    const int tid  = threadIdx.x;
    const int lane = tid & 31;
    const int w    = tid >> 5;
    const int wm   = w >> 2, wn = w & 3;
    const int b    = blockIdx.z;

    int bxv = 0, byv = 0, m0, n0;
    if (SYM) {
        int t = blockIdx.x;
        bxv = (int)floorf((sqrtf(8.0f * t + 1.0f) - 1.0f) * 0.5f);
        while ((bxv + 1) * (bxv + 2) / 2 <= t) ++bxv;
        while (bxv * (bxv + 1) / 2 > t) --bxv;
        byv = t - bxv * (bxv + 1) / 2;
        m0 = byv * BM;
        n0 = bxv * BN;
    } else {
        m0 = blockIdx.y * BM;
        n0 = blockIdx.x * BN;
    }

    const bf16* Ab = A + (size_t)b * sA;
    const bf16* Bb = B + (size_t)b * sB;

    float acc[MT][NT][4];
    #pragma unroll
    for (int i = 0; i < MT; i++)
        #pragma unroll
        for (int j = 0; j < NT; j++)
            #pragma unroll
            for (int q = 0; q < 4; q++) acc[i][j][q] = 0.f;

    auto issue = [&](int kb, int stage) {
        const int k0 = kb * BK;
        const int k0A = MAPA ? (k0 < 2 * T3 ? k0 : k0 - 2 * T3) : k0;
        const int k0B = MAPB ? (k0 < T3 ? k0 : k0 - T3) : k0;  // [hi;hi;lo]->[hi;lo]
        const uint32_t sAst = s0 + stage * STAGE;
        const uint32_t sBst = sAst + A_STAGE;
        if (ATRANS) {
            constexpr int CH = BK * BM / 8;   // 16B chunks
            #pragma unroll
            for (int i = 0; i < CH / 256; i++) {
                int c = tid + i * 256;
                int r = c / (BM / 8), ch = c % (BM / 8);
                const bf16* g = Ab + (size_t)(k0A + r) * LDA + m0 + ch * 8;
                uint32_t s = sAst + r * (BM * 2) + ((ch ^ (r & 7)) << 4);
                cpa16(s, g);
            }
        } else {
            constexpr int CH = BM * BK / 8;
            #pragma unroll
            for (int i = 0; i < CH / 256; i++) {
                int c = tid + i * 256;
                int r = c / CPRA, ch = c % CPRA;
                const bf16* g = Ab + (size_t)(m0 + r) * LDA + k0A + ch * 8;
                uint32_t s = sAst + r * (BK * 2) + ((ch ^ (r & (CPRA - 1))) << 4);
                cpa16(s, g);
            }
        }
        {
            constexpr int CH = BK * BN / 8;
            #pragma unroll
            for (int i = 0; i < CH / 256; i++) {
                int c = tid + i * 256;
                int r = c / (BN / 8), ch = c % (BN / 8);
                const bf16* g = Bb + (size_t)(k0B + r) * N + n0 + ch * 8;
                uint32_t s = sBst + r * (BN * 2) + ((ch ^ (r & 7)) << 4);
                cpa16(s, g);
            }
        }
        asm volatile("cp.async.commit_group;");
    };

    auto compute = [&](int stage) {
        const uint32_t sAst = s0 + stage * STAGE;
        const uint32_t sBst = sAst + A_STAGE;
        #pragma unroll
        for (int ks = 0; ks < BK / 16; ks++) {
            uint32_t afr[MT][4];
            uint32_t bfr[NT][2];
            #pragma unroll
            for (int mt = 0; mt < MT; mt++) {
                if (!ATRANS) {
                    int r  = wm * WM + mt * 16 + (lane & 15);
                    int ch = 2 * ks + (lane >> 4);
                    uint32_t a = sAst + r * (BK * 2) + ((ch ^ (r & (CPRA - 1))) << 4);
                    ldm_x4(afr[mt], a);
                } else {
                    int k  = 16 * ks + (lane & 7) + ((lane >> 4) << 3);
                    int mo = wm * WM + mt * 16 + (((lane >> 3) & 1) << 3);
                    int ch = mo >> 3;
                    uint32_t a = sAst + k * (BM * 2) + ((ch ^ (k & 7)) << 4);
                    ldm_x4_t(afr[mt], a);
                }
            }
            #pragma unroll
            for (int p = 0; p < NT / 2; p++) {
                int k  = 16 * ks + (lane & 15);
                int ch = (wn * WN + p * 16) / 8 + (lane >> 4);
                uint32_t a = sBst + k * (BN * 2) + ((ch ^ (k & 7)) << 4);
                uint32_t r4[4];
                ldm_x4_t(r4, a);
                bfr[2*p][0] = r4[0]; bfr[2*p][1] = r4[1];
                bfr[2*p+1][0] = r4[2]; bfr[2*p+1][1] = r4[3];
            }
            #pragma unroll
            for (int mt = 0; mt < MT; mt++)
                #pragma unroll
                for (int nt = 0; nt < NT; nt++)
                    mma_bf16(acc[mt][nt], afr[mt], bfr[nt]);
        }
    };

    // 3-stage pipeline: compute tile kb while kb+1 stays in flight.
    issue(0, 0);
    if (KB > 1) issue(1, 1);
    for (int kb = 0; kb < KB; kb++) {
        if (kb + 1 < KB) asm volatile("cp.async.wait_group 1;");
        else             asm volatile("cp.async.wait_group 0;");
        __syncthreads();
        if (kb + 2 < KB) issue(kb + 2, (kb + 2) % 3);
        compute(kb % 3);
    }

    // ----------------------- epilogue -----------------------
    float*  Cb  = (MODE == M_CONV2 || MODE == M_TOUT) ? Cp + (size_t)b * sC : nullptr;
    __half* CbH = (MODE == M_ENERGY) ? (__half*)Cp + (size_t)b * sC : nullptr;
    const int er = lane >> 2;
    const int ec = (lane & 3) * 2;

    const bool mirror = SYM && (bxv != byv);
    __half* st = reinterpret_cast<__half*>(smem);   // 128x(128+2) tile
    if (mirror) __syncthreads();   // stages done; reuse smem for transpose

    #pragma unroll
    for (int mt = 0; mt < MT; mt++) {
        #pragma unroll
        for (int half = 0; half < 2; half++) {
            const int lm = wm * WM + mt * 16 + er + half * 8;
            const int gm = m0 + lm;
            float alpha = 0.f, beta = 0.f;
            if (MODE == M_CONV1 || MODE == M_CONV2 || MODE == M_TOUT) {
                alpha = e1[gm]; beta = e2[gm];
            } else if (MODE == M_XV) {
                alpha = e1[gm];
            }
            #pragma unroll
            for (int nt = 0; nt < NT; nt++) {
                const int ln = wn * WN + nt * 8 + ec;
                const int gn = n0 + ln;
                float s0v = acc[mt][nt][half * 2 + 0];
                float s1v = acc[mt][nt][half * 2 + 1];
                float r0, r1;

                if (MODE == M_CONV1 || MODE == M_CONV2) {
                    r0 = fmaxf(fmaf(alpha, s0v, beta), 0.f);
                    r1 = fmaxf(fmaf(alpha, s1v, beta), 0.f);
                } else if (MODE == M_Q || MODE == M_ENERGY) {
                    r0 = s0v; r1 = s1v;
                } else if (MODE == M_XV) {
                    r0 = s0v + alpha; r1 = s1v + alpha;
                } else if (MODE == M_XR) {
                    float d0 = e2[(size_t)b * NP + gn];
                    float d1 = e2[(size_t)b * NP + gn + 1];
                    float h0 = e1[(size_t)b * M * N + (size_t)gm * N + gn];
                    float h1 = e1[(size_t)b * M * N + (size_t)gm * N + gn + 1];
                    r0 = h0 - s0v / (1e-9f + d0);
                    r1 = h1 - s1v / (1e-9f + d1);
                } else { // M_TOUT
                    float t0 = fmaxf(fmaf(alpha, s0v, beta), 0.f);
                    float t1 = fmaxf(fmaf(alpha, s1v, beta), 0.f);
                    r0 = e3[(size_t)b * M * N + (size_t)gm * N + gn] + t0;
                    r1 = e3[(size_t)b * M * N + (size_t)gm * N + gn + 1] + t1;
                }

                if (MODE == M_ENERGY) {
                    __half2 hv = __floats2half2_rn(r0, r1);
                    *(__half2*)&CbH[(size_t)gm * N + gn] = hv;
                    if (mirror) {
                        st[lm * (BN + 2) + ln]     = __low2half(hv);
                        st[lm * (BN + 2) + ln + 1] = __high2half(hv);
                    }
                }
                if (MODE == M_CONV2 || MODE == M_TOUT) {
                    float2 v; v.x = r0; v.y = r1;
                    *(float2*)&Cb[(size_t)gm * N + gn] = v;
                }
                if (MODE == M_TOUT) {
                    float2 v; v.x = r0; v.y = r1;
                    *(float2*)&out2[(size_t)b * 4 * M * N + (size_t)gm * N + gn] = v;
                }

                if (MODE == M_XV) {
                    __nv_bfloat162 hh;
                    hh.x = __float2bfloat16(r0); hh.y = __float2bfloat16(r1);
                    bf16* d = sp1 + (size_t)b * sSp1;
                    *(__nv_bfloat162*)&d[(size_t)gm * N + gn] = hh;
                } else if (MODE == M_CONV1 || MODE == M_CONV2 ||
                           MODE == M_XR || MODE == M_TOUT || MODE == M_Q) {
                    // canonical split [hi;lo]
                    bf16 h0b, l0b, h1b, l1b;
                    split2(r0, h0b, l0b); split2(r1, h1b, l1b);
                    __nv_bfloat162 hh; hh.x = h0b; hh.y = h1b;
                    __nv_bfloat162 ll; ll.x = l0b; ll.y = l1b;
                    bf16* d = sp1 + (size_t)b * sSp1;
                    *(__nv_bfloat162*)&d[(size_t)gm * N + gn] = hh;
                    *(__nv_bfloat162*)&d[(size_t)(M + gm) * N + gn] = ll;
                }
            }
        }
    }

    if (MODE == M_ENERGY && mirror) {
        __syncthreads();
        // write transposed tile: rows [n0, n0+BN), cols [m0, m0+BM)
        #pragma unroll
        for (int pass = 0; pass < (BM * BN) / (256 * 8); pass++) {
            int idx = pass * 256 + tid;
            int j = idx >> 4;            // transposed row 0..127
            int cchunk = (idx & 15) * 8; // col chunk
            __half tmp[8];
            #pragma unroll
            for (int k = 0; k < 8; k++) tmp[k] = st[(cchunk + k) * (BN + 2) + j];
            *(uint4*)&CbH[(size_t)(n0 + j) * N + m0 + cchunk] = *(uint4*)tmp;
        }
    }
}

// smem sizes (BK=64, 3 stages)
constexpr int SMEM_BIG = 3 * (128 * 64 * 2 + 64 * 128 * 2);   // 96 KB
constexpr int SMEM_Q   = 3 * (64 * 64 * 2 + 64 * 128 * 2);    // 72 KB

// ------- row softmax: fp16 energy in, bf16 P out, fused column-sum ----------
// SCALAR layout (tid + k*256): warp atomics hit one 128B line per step —
// the vectorized variant (tid*8+k) was measured 4x slower end-to-end (R5-R7).
__global__ void __launch_bounds__(256) softmax_rows(const __half* __restrict__ E,
                                                    bf16* __restrict__ P,
                                                    float* __restrict__ dcol)
{
    const int tid = threadIdx.x;
    const int row = blockIdx.x;
    const int b   = blockIdx.y;
    const __half* p = E + ((size_t)b * NP + row) * NP;

    float v[8];
    float mx = -3.4e38f;
    #pragma unroll
    for (int k = 0; k < 8; k++) { v[k] = __half2float(p[tid + k*256]); mx = fmaxf(mx, v[k]); }

    #pragma unroll
    for (int o = 16; o > 0; o >>= 1) mx = fmaxf(mx, __shfl_xor_sync(0xffffffffu, mx, o));
    __shared__ float red[8];
    if ((tid & 31) == 0) red[tid >> 5] = mx;
    __syncthreads();
    mx = red[0];
    #pragma unroll
    for (int w = 1; w < 8; w++) mx = fmaxf(mx, red[w]);

    float s = 0.f;
    #pragma unroll
    for (int k = 0; k < 8; k++) { v[k] = __expf(v[k] - mx); s += v[k]; }
    #pragma unroll
    for (int o = 16; o > 0; o >>= 1) s += __shfl_xor_sync(0xffffffffu, s, o);
    __syncthreads();
    if ((tid & 31) == 0) red[tid >> 5] = s;
    __syncthreads();
    s = red[0];
    #pragma unroll
    for (int w = 1; w < 8; w++) s += red[w];

    const float inv = 1.f / s;
    bf16* po = P + ((size_t)b * NP + row) * NP;
    float* dc = dcol + (size_t)b * NP;
    #pragma unroll
    for (int k = 0; k < 8; k++) {
        int n = tid + k * 256;
        bf16 pb = __float2bfloat16(v[k] * inv);
        po[n] = pb;
        atomicAdd(&dc[n], __bfloat162float(pb));
    }
}

__global__ void zero_d_kernel(float* d) { d[blockIdx.x * 256 + threadIdx.x] = 0.f; }

// ---------------- launch -----------------------------------------------------
extern "C" void kernel_launch(void* const* d_in, const int* in_sizes, int n_in,
                              void* d_out, int out_size)
{
    const float* x       = (const float*)d_in[0];
    const float* conv1_w = (const float*)d_in[1];
    const float* conv2_w = (const float*)d_in[2];
    const float* bn1_g = (const float*)d_in[3];
    const float* bn1_b = (const float*)d_in[4];
    const float* bn1_m = (const float*)d_in[5];
    const float* bn1_v = (const float*)d_in[6];
    const float* bn2_g = (const float*)d_in[7];
    const float* bn2_b = (const float*)d_in[8];
    const float* bn2_m = (const float*)d_in[9];
    const float* bn2_v = (const float*)d_in[10];
    const float* sa_qk_w = (const float*)d_in[11];
    const float* sa_v_w  = (const float*)d_in[12];
    const float* sa_v_b  = (const float*)d_in[13];
    const float* sa_t_w  = (const float*)d_in[14];
    const float* sa_t_b  = (const float*)d_in[15];
    const float* sa_g    = (const float*)d_in[16];
    const float* sa_b    = (const float*)d_in[17];
    const float* sa_m    = (const float*)d_in[18];
    const float* sa_var  = (const float*)d_in[19];
    float* out = (float*)d_out;

    float *h0, *h1, *dcol, *bnp;
    __half* energy;
    bf16 *xB, *hB0, *hB1, *qbuf, *Pb, *xv, *uB, *wA;
    cudaGetSymbolAddress((void**)&h0,     g_h0);
    cudaGetSymbolAddress((void**)&h1,     g_h1);
    cudaGetSymbolAddress((void**)&energy, g_energy);
    cudaGetSymbolAddress((void**)&dcol,   g_d);
    cudaGetSymbolAddress((void**)&bnp,    g_bnp);
    cudaGetSymbolAddress((void**)&xB,     g_xB);
    cudaGetSymbolAddress((void**)&hB0,    g_hB0);
    cudaGetSymbolAddress((void**)&hB1,    g_hB1);
    cudaGetSymbolAddress((void**)&qbuf,   g_q);
    cudaGetSymbolAddress((void**)&Pb,     g_P);
    cudaGetSymbolAddress((void**)&xv,     g_xv);
    cudaGetSymbolAddress((void**)&uB,     g_uB);
    cudaGetSymbolAddress((void**)&wA,     g_wA);

    const size_t sB2 = (size_t)2 * C * NP;     // [hi;lo] B-form stride (512x2048)
    const size_t sQ2 = (size_t)2 * CQ * NP;    // q split stride (128x2048)
    const size_t sP  = (size_t)NP * NP;
    const size_t sHN = (size_t)C * NP;

    // opt in to >48KB dynamic smem (immediate driver calls; not graph-captured)
    cudaFuncSetAttribute(gemm_bf16<256, 2048, 768, 128, 128, false, M_CONV1, true, true>,
                         cudaFuncAttributeMaxDynamicSharedMemorySize, SMEM_BIG);
    cudaFuncSetAttribute(gemm_bf16<256, 2048, 768, 128, 128, false, M_CONV2, true, true>,
                         cudaFuncAttributeMaxDynamicSharedMemorySize, SMEM_BIG);
    cudaFuncSetAttribute(gemm_bf16<64, 2048, 768, 64, 128, false, M_Q, true, true>,
                         cudaFuncAttributeMaxDynamicSharedMemorySize, SMEM_Q);
    cudaFuncSetAttribute(gemm_bf16<2048, 2048, 192, 128, 128, true, M_ENERGY, true, true, true>,
                         cudaFuncAttributeMaxDynamicSharedMemorySize, SMEM_BIG);
    cudaFuncSetAttribute(gemm_bf16<256, 2048, 768, 128, 128, false, M_XV, true, true>,
                         cudaFuncAttributeMaxDynamicSharedMemorySize, SMEM_BIG);
    cudaFuncSetAttribute(gemm_bf16<256, 2048, 2048, 128, 128, false, M_XR, false, false>,
                         cudaFuncAttributeMaxDynamicSharedMemorySize, SMEM_BIG);
    cudaFuncSetAttribute(gemm_bf16<256, 2048, 768, 128, 128, false, M_TOUT, true, true>,
                         cudaFuncAttributeMaxDynamicSharedMemorySize, SMEM_BIG);

    bn_prep<<<6, 256>>>(bn1_g, bn1_b, bn1_m, bn1_v,
                        bn2_g, bn2_b, bn2_m, bn2_v,
                        sa_g, sa_b, sa_m, sa_var, sa_t_b);

    wsplit_all<<<2816, 256>>>(conv1_w, conv2_w, sa_qk_w, sa_v_w, sa_t_w);

    xsplitB<<<(BATCH * C * NP) / 256, 256>>>(x, xB);

    // conv1: split-only -> hB0
    gemm_bf16<256, 2048, 768, 128, 128, false, M_CONV1, true, true>
        <<<dim3(16, 2, BATCH), 256, SMEM_BIG>>>(wA + (size_t)0 * 512, 0, xB, sB2,
                                      nullptr, 0, bnp + 0, bnp + C, nullptr, nullptr,
                                      hB0, sB2);
    // conv2: fp32 h0 + split hB1
    gemm_bf16<256, 2048, 768, 128, 128, false, M_CONV2, true, true>
        <<<dim3(16, 2, BATCH), 256, SMEM_BIG>>>(wA + (size_t)256 * 512, 0, hB0, sB2,
                                      h0, sHN, bnp + 2*C, bnp + 3*C, nullptr, nullptr,
                                      hB1, sB2);

    float* hcur = h0;
    float* hnxt = h1;
    bf16* hBcur = hB1;
    bf16* hBnxt = hB0;
    for (int i = 0; i < 4; i++) {
        // q (split [hi;lo]) -> qbuf   (contract over C=256 -> K3=768)
        gemm_bf16<64, 2048, 768, 64, 128, false, M_Q, true, true>
            <<<dim3(16, 1, BATCH), 256, SMEM_Q>>>(wA + (size_t)(512 + i*64) * 512, 0,
                                          hBcur, sB2,
                                          nullptr, 0, nullptr, nullptr, nullptr, nullptr,
                                          qbuf, sQ2);
        // energy = q^T q, symmetric: only upper-triangle block pairs (136 of 256)
        gemm_bf16<2048, 2048, 192, 128, 128, true, M_ENERGY, true, true, true>
            <<<dim3(136, 1, BATCH), 256, SMEM_BIG>>>(qbuf, sQ2, qbuf, sQ2,
                                           (float*)energy, sP, nullptr, nullptr, nullptr,
                                           nullptr, nullptr, 0);
        // softmax + fused column-sum (scalar layout)
        zero_d_kernel<<<BATCH * NP / 256, 256>>>(dcol);
        softmax_rows<<<dim3(NP, BATCH), 256>>>(energy, Pb, dcol);
        // xv = v_w @ h + v_b -> plain bf16
        gemm_bf16<256, 2048, 768, 128, 128, false, M_XV, true, true>
            <<<dim3(16, 2, BATCH), 256, SMEM_BIG>>>(wA + (size_t)(768 + i*256) * 512, 0,
                                          hBcur, sB2,
                                          nullptr, 0, sa_v_b + (size_t)i * C, nullptr,
                                          nullptr, nullptr, xv, sHN);
        // u = h - (xv @ P)/(1e-9+d) -> uB split (pure bf16 GEMM, K=2048)
        gemm_bf16<256, 2048, 2048, 128, 128, false, M_XR, false, false>
            <<<dim3(16, 2, BATCH), 256, SMEM_BIG>>>(xv, sHN, Pb, sP,
                                          nullptr, 0, hcur, dcol, nullptr, nullptr,
                                          uB, sB2);
        // h_next = h + relu(bn(t_w @ u)); out slice + fp32 hnxt + split hBnxt
        gemm_bf16<256, 2048, 768, 128, 128, false, M_TOUT, true, true>
            <<<dim3(16, 2, BATCH), 256, SMEM_BIG>>>(wA + (size_t)(1792 + i*256) * 512, 0,
                                          uB, sB2,
                                          hnxt, sHN, bnp + (4+i)*C, bnp + (8+i)*C, hcur,
                                          out + (size_t)i * C * NP,
                                          hBnxt, sB2);
        float* tf = hcur; hcur = hnxt; hnxt = tf;
        bf16* tb = hBcur; hBcur = hBnxt; hBnxt = tb;
    }
    (void)in_sizes; (void)n_in; (void)out_size;
}

// round 13
// speedup vs baseline: 1.0205x; 1.0205x over previous
#include <cuda_runtime.h>
#include <cuda_bf16.h>
#include <cuda_fp16.h>
#include <cstdint>
#include <cstddef>

using bf16 = __nv_bfloat16;

constexpr int BATCH = 16;
constexpr int C     = 256;
constexpr int NP    = 2048;
constexpr int CQ    = 64;
constexpr float EPSBN = 1e-3f;

// ---------------- scratch (static device buffers; no allocation) -------------
__device__ float  g_h0[BATCH * C * NP];
__device__ float  g_h1[BATCH * C * NP];
__device__ __half g_energy[(size_t)BATCH * NP * NP];            // 134 MB
__device__ bf16   g_P     [(size_t)BATCH * NP * NP];            // 134 MB
__device__ bf16   g_xB [(size_t)BATCH * 2 * C * NP];            // [hi;lo]
__device__ bf16   g_hB0[(size_t)BATCH * 2 * C * NP];
__device__ bf16   g_hB1[(size_t)BATCH * 2 * C * NP];
__device__ bf16   g_q  [(size_t)BATCH * 2 * CQ * NP];           // [hi;lo]
__device__ bf16   g_xv [(size_t)BATCH * C * NP];                // plain bf16
__device__ bf16   g_uB [(size_t)BATCH * 2 * C * NP];
__device__ float  g_d  [BATCH * NP];
__device__ float  g_dinv[BATCH * NP];
__device__ float  g_bnp[12 * C];
// weight splits [hi(256)|lo(256)]: rows: conv1 0..255, conv2 256..511, qk 512..767,
// v 768..1791, t 1792..2815
__device__ bf16   g_wA [(size_t)2816 * 512];

// ---------------- BN prefold -------------------------------------------------
__global__ void bn_prep(const float* g1, const float* b1, const float* m1, const float* v1,
                        const float* g2, const float* b2, const float* m2, const float* v2,
                        const float* sg, const float* sb, const float* sm, const float* sv,
                        const float* stb)
{
    int c = threadIdx.x;
    int w = blockIdx.x;
    if (w == 0) {
        float a = g1[c] * rsqrtf(v1[c] + EPSBN);
        g_bnp[c] = a; g_bnp[C + c] = b1[c] - m1[c] * a;
    } else if (w == 1) {
        float a = g2[c] * rsqrtf(v2[c] + EPSBN);
        g_bnp[2*C + c] = a; g_bnp[3*C + c] = b2[c] - m2[c] * a;
    } else {
        int i = w - 2;
        float a = sg[i*C + c] * rsqrtf(sv[i*C + c] + EPSBN);
        g_bnp[(4+i)*C + c] = a;
        g_bnp[(8+i)*C + c] = sb[i*C + c] - sm[i*C + c] * a + a * stb[i*C + c];
    }
}

// ---------------- split helpers ---------------------------------------------
__device__ __forceinline__ void split2(float v, bf16& hi, bf16& lo)
{
    hi = __float2bfloat16(v);
    lo = __float2bfloat16(v - __bfloat162float(hi));
}

// ALL weights in one launch: rows 0..255 conv1, 256..511 conv2, 512..767 qk,
// 768..1791 v, 1792..2815 t.
__global__ void wsplit_all(const float* __restrict__ c1, const float* __restrict__ c2,
                           const float* __restrict__ qk, const float* __restrict__ vw,
                           const float* __restrict__ tw)
{
    int idx = blockIdx.x * 256 + threadIdx.x;   // 0 .. 2816*256-1
    int row = idx >> 8, k = idx & 255;
    const float* src;
    int r;
    if (row < 256)       { src = c1; r = row; }
    else if (row < 512)  { src = c2; r = row - 256; }
    else if (row < 768)  { src = qk; r = row - 512; }
    else if (row < 1792) { src = vw; r = row - 768; }
    else                 { src = tw; r = row - 1792; }
    bf16 hi, lo; split2(src[r * 256 + k], hi, lo);
    bf16* d = g_wA + (size_t)row * 512;
    d[k] = hi; d[256 + k] = lo;
}

// x: src fp32 [B,C,NP] -> dst bf16 [B,2C,NP] = [hi;lo]
__global__ void xsplitB(const float* __restrict__ src, bf16* __restrict__ dst)
{
    size_t idx = (size_t)blockIdx.x * 256 + threadIdx.x;
    int b = (int)(idx / ((size_t)C * NP));
    size_t rem = idx - (size_t)b * C * NP;
    bf16 hi, lo; split2(src[idx], hi, lo);
    bf16* d = dst + (size_t)b * 2 * C * NP;
    d[rem] = hi; d[(size_t)C * NP + rem] = lo;
}

// ---------------- mma.sync bf16 GEMM with fused epilogues --------------------
enum { M_CONV1 = 0, M_CONV2, M_Q, M_ENERGY, M_XV, M_XR, M_TOUT };

__device__ __forceinline__ void ldm_x4(uint32_t* r, uint32_t a)
{
    asm volatile("ldmatrix.sync.aligned.m8n8.x4.shared.b16 {%0,%1,%2,%3}, [%4];"
                 : "=r"(r[0]), "=r"(r[1]), "=r"(r[2]), "=r"(r[3]) : "r"(a));
}
__device__ __forceinline__ void ldm_x4_t(uint32_t* r, uint32_t a)
{
    asm volatile("ldmatrix.sync.aligned.m8n8.x4.trans.shared.b16 {%0,%1,%2,%3}, [%4];"
                 : "=r"(r[0]), "=r"(r[1]), "=r"(r[2]), "=r"(r[3]) : "r"(a));
}
__device__ __forceinline__ void cpa16(uint32_t s, const void* g)
{
    asm volatile("cp.async.cg.shared.global [%0], [%1], 16;" :: "r"(s), "l"(g));
}
__device__ __forceinline__ void mma_bf16(float* c, const uint32_t* a, const uint32_t* b)
{
    asm volatile("mma.sync.aligned.m16n8k16.row.col.f32.bf16.bf16.f32 "
                 "{%0,%1,%2,%3}, {%4,%5,%6,%7}, {%8,%9}, {%0,%1,%2,%3};"
                 : "+f"(c[0]), "+f"(c[1]), "+f"(c[2]), "+f"(c[3])
                 : "r"(a[0]), "r"(a[1]), "r"(a[2]), "r"(a[3]), "r"(b[0]), "r"(b[1]));
}

// MAPA: A logical k-thirds [hi|lo|hi] stored [hi|lo]  (phys K = 2*K3/3)
// MAPB: B logical k-thirds [hi;hi;lo] stored [hi;lo]
// SYM:  symmetric NxN product (energy); off-diagonal tiles mirrored via smem.
// BK=64, 2-stage, wait_group 0 — validated optimum (R10 win; 3-stage regressed
// twice, R5/R11: extra stage shrinks L1D carveout on an L1TEX-co-bound loop).
template<int M, int N, int K3, int BM, int BN, bool ATRANS, int MODE,
         bool MAPA, bool MAPB, bool SYM = false>
__global__ void __launch_bounds__(256, 2)
gemm_bf16(const bf16* __restrict__ A, size_t sA,
          const bf16* __restrict__ B, size_t sB,
          float* __restrict__ Cp, size_t sC,
          const float* __restrict__ e1, const float* __restrict__ e2,
          const float* __restrict__ e3, float* __restrict__ out2,
          bf16* __restrict__ sp1, size_t sSp1)
{
    constexpr int BK = 64;
    constexpr int KB = K3 / BK;
    constexpr int T3 = K3 / 3;
    constexpr int WM = BM / 2, WN = BN / 4;
    constexpr int MT = WM / 16, NT = WN / 8;
    constexpr int A_STAGE = BM * BK * 2;      // bytes
    constexpr int B_STAGE = BK * BN * 2;
    constexpr int STAGE   = A_STAGE + B_STAGE;
    constexpr int CPRA = BK / 8;              // 16B chunks per A row (non-trans)
    constexpr int LDA = ATRANS ? M : (MAPA ? 2 * T3 : K3);

    extern __shared__ __align__(16) uint8_t smem[];
    const uint32_t s0 = (uint32_t)__cvta_generic_to_shared(smem);

    const int tid  = threadIdx.x;
    const int lane = tid & 31;
    const int w    = tid >> 5;
    const int wm   = w >> 2, wn = w & 3;
    const int b    = blockIdx.z;

    int bxv = 0, byv = 0, m0, n0;
    if (SYM) {
        int t = blockIdx.x;
        bxv = (int)floorf((sqrtf(8.0f * t + 1.0f) - 1.0f) * 0.5f);
        while ((bxv + 1) * (bxv + 2) / 2 <= t) ++bxv;
        while (bxv * (bxv + 1) / 2 > t) --bxv;
        byv = t - bxv * (bxv + 1) / 2;
        m0 = byv * BM;
        n0 = bxv * BN;
    } else {
        m0 = blockIdx.y * BM;
        n0 = blockIdx.x * BN;
    }

    const bf16* Ab = A + (size_t)b * sA;
    const bf16* Bb = B + (size_t)b * sB;

    float acc[MT][NT][4];
    #pragma unroll
    for (int i = 0; i < MT; i++)
        #pragma unroll
        for (int j = 0; j < NT; j++)
            #pragma unroll
            for (int q = 0; q < 4; q++) acc[i][j][q] = 0.f;

    auto issue = [&](int kb, int stage) {
        const int k0 = kb * BK;
        const int k0A = MAPA ? (k0 < 2 * T3 ? k0 : k0 - 2 * T3) : k0;
        const int k0B = MAPB ? (k0 < T3 ? k0 : k0 - T3) : k0;  // [hi;hi;lo]->[hi;lo]
        const uint32_t sAst = s0 + stage * STAGE;
        const uint32_t sBst = sAst + A_STAGE;
        if (ATRANS) {
            constexpr int CH = BK * BM / 8;   // 16B chunks
            #pragma unroll
            for (int i = 0; i < CH / 256; i++) {
                int c = tid + i * 256;
                int r = c / (BM / 8), ch = c % (BM / 8);
                const bf16* g = Ab + (size_t)(k0A + r) * LDA + m0 + ch * 8;
                uint32_t s = sAst + r * (BM * 2) + ((ch ^ (r & 7)) << 4);
                cpa16(s, g);
            }
        } else {
            constexpr int CH = BM * BK / 8;
            #pragma unroll
            for (int i = 0; i < CH / 256; i++) {
                int c = tid + i * 256;
                int r = c / CPRA, ch = c % CPRA;
                const bf16* g = Ab + (size_t)(m0 + r) * LDA + k0A + ch * 8;
                uint32_t s = sAst + r * (BK * 2) + ((ch ^ (r & (CPRA - 1))) << 4);
                cpa16(s, g);
            }
        }
        {
            constexpr int CH = BK * BN / 8;
            #pragma unroll
            for (int i = 0; i < CH / 256; i++) {
                int c = tid + i * 256;
                int r = c / (BN / 8), ch = c % (BN / 8);
                const bf16* g = Bb + (size_t)(k0B + r) * N + n0 + ch * 8;
                uint32_t s = sBst + r * (BN * 2) + ((ch ^ (r & 7)) << 4);
                cpa16(s, g);
            }
        }
        asm volatile("cp.async.commit_group;");
    };

    auto compute = [&](int stage) {
        const uint32_t sAst = s0 + stage * STAGE;
        const uint32_t sBst = sAst + A_STAGE;
        #pragma unroll
        for (int ks = 0; ks < BK / 16; ks++) {
            uint32_t afr[MT][4];
            uint32_t bfr[NT][2];
            #pragma unroll
            for (int mt = 0; mt < MT; mt++) {
                if (!ATRANS) {
                    int r  = wm * WM + mt * 16 + (lane & 15);
                    int ch = 2 * ks + (lane >> 4);
                    uint32_t a = sAst + r * (BK * 2) + ((ch ^ (r & (CPRA - 1))) << 4);
                    ldm_x4(afr[mt], a);
                } else {
                    int k  = 16 * ks + (lane & 7) + ((lane >> 4) << 3);
                    int mo = wm * WM + mt * 16 + (((lane >> 3) & 1) << 3);
                    int ch = mo >> 3;
                    uint32_t a = sAst + k * (BM * 2) + ((ch ^ (k & 7)) << 4);
                    ldm_x4_t(afr[mt], a);
                }
            }
            #pragma unroll
            for (int p = 0; p < NT / 2; p++) {
                int k  = 16 * ks + (lane & 15);
                int ch = (wn * WN + p * 16) / 8 + (lane >> 4);
                uint32_t a = sBst + k * (BN * 2) + ((ch ^ (k & 7)) << 4);
                uint32_t r4[4];
                ldm_x4_t(r4, a);
                bfr[2*p][0] = r4[0]; bfr[2*p][1] = r4[1];
                bfr[2*p+1][0] = r4[2]; bfr[2*p+1][1] = r4[3];
            }
            #pragma unroll
            for (int mt = 0; mt < MT; mt++)
                #pragma unroll
                for (int nt = 0; nt < NT; nt++)
                    mma_bf16(acc[mt][nt], afr[mt], bfr[nt]);
        }
    };

    issue(0, 0);
    for (int kb = 0; kb < KB; kb++) {
        asm volatile("cp.async.wait_group 0;");
        __syncthreads();
        if (kb + 1 < KB) issue(kb + 1, (kb + 1) & 1);
        compute(kb & 1);
    }

    // ----------------------- epilogue -----------------------
    float*  Cb  = (MODE == M_CONV2 || MODE == M_TOUT) ? Cp + (size_t)b * sC : nullptr;
    __half* CbH = (MODE == M_ENERGY) ? (__half*)Cp + (size_t)b * sC : nullptr;
    const int er = lane >> 2;
    const int ec = (lane & 3) * 2;

    const bool mirror = SYM && (bxv != byv);
    __half* st = reinterpret_cast<__half*>(smem);   // 128x(128+2) tile
    if (mirror) __syncthreads();   // stages done; reuse smem for transpose

    #pragma unroll
    for (int mt = 0; mt < MT; mt++) {
        #pragma unroll
        for (int half = 0; half < 2; half++) {
            const int lm = wm * WM + mt * 16 + er + half * 8;
            const int gm = m0 + lm;
            float alpha = 0.f, beta = 0.f;
            if (MODE == M_CONV1 || MODE == M_CONV2 || MODE == M_TOUT) {
                alpha = e1[gm]; beta = e2[gm];
            } else if (MODE == M_XV) {
                alpha = e1[gm];
            }
            #pragma unroll
            for (int nt = 0; nt < NT; nt++) {
                const int ln = wn * WN + nt * 8 + ec;
                const int gn = n0 + ln;
                float s0v = acc[mt][nt][half * 2 + 0];
                float s1v = acc[mt][nt][half * 2 + 1];
                float r0, r1;

                if (MODE == M_CONV1 || MODE == M_CONV2) {
                    r0 = fmaxf(fmaf(alpha, s0v, beta), 0.f);
                    r1 = fmaxf(fmaf(alpha, s1v, beta), 0.f);
                } else if (MODE == M_Q || MODE == M_ENERGY) {
                    r0 = s0v; r1 = s1v;
                } else if (MODE == M_XV) {
                    r0 = s0v + alpha; r1 = s1v + alpha;
                } else if (MODE == M_XR) {
                    // e2 = precomputed 1/(1e-9+d): multiply instead of divide
                    float i0 = e2[(size_t)b * NP + gn];
                    float i1 = e2[(size_t)b * NP + gn + 1];
                    float h0 = e1[(size_t)b * M * N + (size_t)gm * N + gn];
                    float h1 = e1[(size_t)b * M * N + (size_t)gm * N + gn + 1];
                    r0 = fmaf(-s0v, i0, h0);
                    r1 = fmaf(-s1v, i1, h1);
                } else { // M_TOUT
                    float t0 = fmaxf(fmaf(alpha, s0v, beta), 0.f);
                    float t1 = fmaxf(fmaf(alpha, s1v, beta), 0.f);
                    r0 = e3[(size_t)b * M * N + (size_t)gm * N + gn] + t0;
                    r1 = e3[(size_t)b * M * N + (size_t)gm * N + gn + 1] + t1;
                }

                if (MODE == M_ENERGY) {
                    __half2 hv = __floats2half2_rn(r0, r1);
                    *(__half2*)&CbH[(size_t)gm * N + gn] = hv;
                    if (mirror) {
                        st[lm * (BN + 2) + ln]     = __low2half(hv);
                        st[lm * (BN + 2) + ln + 1] = __high2half(hv);
                    }
                }
                if (MODE == M_CONV2 || MODE == M_TOUT) {
                    float2 v; v.x = r0; v.y = r1;
                    *(float2*)&Cb[(size_t)gm * N + gn] = v;
                }
                if (MODE == M_TOUT) {
                    float2 v; v.x = r0; v.y = r1;
                    *(float2*)&out2[(size_t)b * 4 * M * N + (size_t)gm * N + gn] = v;
                }

                if (MODE == M_XV) {
                    __nv_bfloat162 hh;
                    hh.x = __float2bfloat16(r0); hh.y = __float2bfloat16(r1);
                    bf16* d = sp1 + (size_t)b * sSp1;
                    *(__nv_bfloat162*)&d[(size_t)gm * N + gn] = hh;
                } else if (MODE == M_CONV1 || MODE == M_CONV2 ||
                           MODE == M_XR || MODE == M_TOUT || MODE == M_Q) {
                    // canonical split [hi;lo]
                    bf16 h0b, l0b, h1b, l1b;
                    split2(r0, h0b, l0b); split2(r1, h1b, l1b);
                    __nv_bfloat162 hh; hh.x = h0b; hh.y = h1b;
                    __nv_bfloat162 ll; ll.x = l0b; ll.y = l1b;
                    bf16* d = sp1 + (size_t)b * sSp1;
                    *(__nv_bfloat162*)&d[(size_t)gm * N + gn] = hh;
                    *(__nv_bfloat162*)&d[(size_t)(M + gm) * N + gn] = ll;
                }
            }
        }
    }

    if (MODE == M_ENERGY && mirror) {
        __syncthreads();
        // write transposed tile: rows [n0, n0+BN), cols [m0, m0+BM)
        #pragma unroll
        for (int pass = 0; pass < (BM * BN) / (256 * 8); pass++) {
            int idx = pass * 256 + tid;
            int j = idx >> 4;            // transposed row 0..127
            int cchunk = (idx & 15) * 8; // col chunk
            __half tmp[8];
            #pragma unroll
            for (int k = 0; k < 8; k++) tmp[k] = st[(cchunk + k) * (BN + 2) + j];
            *(uint4*)&CbH[(size_t)(n0 + j) * N + m0 + cchunk] = *(uint4*)tmp;
        }
    }
}

// smem sizes (BK=64, 2 stages)
constexpr int SMEM_BIG = 2 * (128 * 64 * 2 + 64 * 128 * 2);   // 64 KB
constexpr int SMEM_Q   = 2 * (64 * 64 * 2 + 64 * 128 * 2);    // 48 KB

// ------- row softmax: fp16 energy in, bf16 P out, fused column-sum ----------
// SCALAR layout (tid + k*256): warp atomics hit one 128B line per step —
// the vectorized variant (tid*8+k) was measured 4x slower end-to-end (R5-R7).
__global__ void __launch_bounds__(256) softmax_rows(const __half* __restrict__ E,
                                                    bf16* __restrict__ P,
                                                    float* __restrict__ dcol)
{
    const int tid = threadIdx.x;
    const int row = blockIdx.x;
    const int b   = blockIdx.y;
    const __half* p = E + ((size_t)b * NP + row) * NP;

    float v[8];
    float mx = -3.4e38f;
    #pragma unroll
    for (int k = 0; k < 8; k++) { v[k] = __half2float(p[tid + k*256]); mx = fmaxf(mx, v[k]); }

    #pragma unroll
    for (int o = 16; o > 0; o >>= 1) mx = fmaxf(mx, __shfl_xor_sync(0xffffffffu, mx, o));
    __shared__ float red[8];
    if ((tid & 31) == 0) red[tid >> 5] = mx;
    __syncthreads();
    mx = red[0];
    #pragma unroll
    for (int w = 1; w < 8; w++) mx = fmaxf(mx, red[w]);

    float s = 0.f;
    #pragma unroll
    for (int k = 0; k < 8; k++) { v[k] = __expf(v[k] - mx); s += v[k]; }
    #pragma unroll
    for (int o = 16; o > 0; o >>= 1) s += __shfl_xor_sync(0xffffffffu, s, o);
    __syncthreads();
    if ((tid & 31) == 0) red[tid >> 5] = s;
    __syncthreads();
    s = red[0];
    #pragma unroll
    for (int w = 1; w < 8; w++) s += red[w];

    const float inv = 1.f / s;
    bf16* po = P + ((size_t)b * NP + row) * NP;
    float* dc = dcol + (size_t)b * NP;
    #pragma unroll
    for (int k = 0; k < 8; k++) {
        int n = tid + k * 256;
        bf16 pb = __float2bfloat16(v[k] * inv);
        po[n] = pb;
        atomicAdd(&dc[n], __bfloat162float(pb));
    }
}

__global__ void zero_d_kernel(float* d) { d[blockIdx.x * 256 + threadIdx.x] = 0.f; }

// inv_d = 1/(1e-9 + d), so XR epilogue multiplies instead of dividing
__global__ void rcp_d_kernel(const float* __restrict__ d, float* __restrict__ dinv)
{
    int i = blockIdx.x * 256 + threadIdx.x;
    dinv[i] = __frcp_rn(1e-9f + d[i]);
}

// ---------------- launch -----------------------------------------------------
extern "C" void kernel_launch(void* const* d_in, const int* in_sizes, int n_in,
                              void* d_out, int out_size)
{
    const float* x       = (const float*)d_in[0];
    const float* conv1_w = (const float*)d_in[1];
    const float* conv2_w = (const float*)d_in[2];
    const float* bn1_g = (const float*)d_in[3];
    const float* bn1_b = (const float*)d_in[4];
    const float* bn1_m = (const float*)d_in[5];
    const float* bn1_v = (const float*)d_in[6];
    const float* bn2_g = (const float*)d_in[7];
    const float* bn2_b = (const float*)d_in[8];
    const float* bn2_m = (const float*)d_in[9];
    const float* bn2_v = (const float*)d_in[10];
    const float* sa_qk_w = (const float*)d_in[11];
    const float* sa_v_w  = (const float*)d_in[12];
    const float* sa_v_b  = (const float*)d_in[13];
    const float* sa_t_w  = (const float*)d_in[14];
    const float* sa_t_b  = (const float*)d_in[15];
    const float* sa_g    = (const float*)d_in[16];
    const float* sa_b    = (const float*)d_in[17];
    const float* sa_m    = (const float*)d_in[18];
    const float* sa_var  = (const float*)d_in[19];
    float* out = (float*)d_out;

    float *h0, *h1, *dcol, *dinv, *bnp;
    __half* energy;
    bf16 *xB, *hB0, *hB1, *qbuf, *Pb, *xv, *uB, *wA;
    cudaGetSymbolAddress((void**)&h0,     g_h0);
    cudaGetSymbolAddress((void**)&h1,     g_h1);
    cudaGetSymbolAddress((void**)&energy, g_energy);
    cudaGetSymbolAddress((void**)&dcol,   g_d);
    cudaGetSymbolAddress((void**)&dinv,   g_dinv);
    cudaGetSymbolAddress((void**)&bnp,    g_bnp);
    cudaGetSymbolAddress((void**)&xB,     g_xB);
    cudaGetSymbolAddress((void**)&hB0,    g_hB0);
    cudaGetSymbolAddress((void**)&hB1,    g_hB1);
    cudaGetSymbolAddress((void**)&qbuf,   g_q);
    cudaGetSymbolAddress((void**)&Pb,     g_P);
    cudaGetSymbolAddress((void**)&xv,     g_xv);
    cudaGetSymbolAddress((void**)&uB,     g_uB);
    cudaGetSymbolAddress((void**)&wA,     g_wA);

    const size_t sB2 = (size_t)2 * C * NP;     // [hi;lo] B-form stride (512x2048)
    const size_t sQ2 = (size_t)2 * CQ * NP;    // q split stride (128x2048)
    const size_t sP  = (size_t)NP * NP;
    const size_t sHN = (size_t)C * NP;

    // opt in to >48KB dynamic smem (immediate driver calls; not graph-captured)
    cudaFuncSetAttribute(gemm_bf16<256, 2048, 768, 128, 128, false, M_CONV1, true, true>,
                         cudaFuncAttributeMaxDynamicSharedMemorySize, SMEM_BIG);
    cudaFuncSetAttribute(gemm_bf16<256, 2048, 768, 128, 128, false, M_CONV2, true, true>,
                         cudaFuncAttributeMaxDynamicSharedMemorySize, SMEM_BIG);
    cudaFuncSetAttribute(gemm_bf16<64, 2048, 768, 64, 128, false, M_Q, true, true>,
                         cudaFuncAttributeMaxDynamicSharedMemorySize, SMEM_Q);
    cudaFuncSetAttribute(gemm_bf16<2048, 2048, 192, 128, 128, true, M_ENERGY, true, true, true>,
                         cudaFuncAttributeMaxDynamicSharedMemorySize, SMEM_BIG);
    cudaFuncSetAttribute(gemm_bf16<256, 2048, 768, 128, 128, false, M_XV, true, true>,
                         cudaFuncAttributeMaxDynamicSharedMemorySize, SMEM_BIG);
    cudaFuncSetAttribute(gemm_bf16<256, 2048, 2048, 128, 128, false, M_XR, false, false>,
                         cudaFuncAttributeMaxDynamicSharedMemorySize, SMEM_BIG);
    cudaFuncSetAttribute(gemm_bf16<256, 2048, 768, 128, 128, false, M_TOUT, true, true>,
                         cudaFuncAttributeMaxDynamicSharedMemorySize, SMEM_BIG);

    bn_prep<<<6, 256>>>(bn1_g, bn1_b, bn1_m, bn1_v,
                        bn2_g, bn2_b, bn2_m, bn2_v,
                        sa_g, sa_b, sa_m, sa_var, sa_t_b);

    wsplit_all<<<2816, 256>>>(conv1_w, conv2_w, sa_qk_w, sa_v_w, sa_t_w);

    xsplitB<<<(BATCH * C * NP) / 256, 256>>>(x, xB);

    // conv1: split-only -> hB0
    gemm_bf16<256, 2048, 768, 128, 128, false, M_CONV1, true, true>
        <<<dim3(16, 2, BATCH), 256, SMEM_BIG>>>(wA + (size_t)0 * 512, 0, xB, sB2,
                                      nullptr, 0, bnp + 0, bnp + C, nullptr, nullptr,
                                      hB0, sB2);
    // conv2: fp32 h0 + split hB1
    gemm_bf16<256, 2048, 768, 128, 128, false, M_CONV2, true, true>
        <<<dim3(16, 2, BATCH), 256, SMEM_BIG>>>(wA + (size_t)256 * 512, 0, hB0, sB2,
                                      h0, sHN, bnp + 2*C, bnp + 3*C, nullptr, nullptr,
                                      hB1, sB2);

    float* hcur = h0;
    float* hnxt = h1;
    bf16* hBcur = hB1;
    bf16* hBnxt = hB0;
    for (int i = 0; i < 4; i++) {
        // q (split [hi;lo]) -> qbuf   (contract over C=256 -> K3=768)
        gemm_bf16<64, 2048, 768, 64, 128, false, M_Q, true, true>
            <<<dim3(16, 1, BATCH), 256, SMEM_Q>>>(wA + (size_t)(512 + i*64) * 512, 0,
                                          hBcur, sB2,
                                          nullptr, 0, nullptr, nullptr, nullptr, nullptr,
                                          qbuf, sQ2);
        // energy = q^T q, symmetric: only upper-triangle block pairs (136 of 256)
        gemm_bf16<2048, 2048, 192, 128, 128, true, M_ENERGY, true, true, true>
            <<<dim3(136, 1, BATCH), 256, SMEM_BIG>>>(qbuf, sQ2, qbuf, sQ2,
                                           (float*)energy, sP, nullptr, nullptr, nullptr,
                                           nullptr, nullptr, 0);
        // softmax + fused column-sum (scalar layout), then reciprocal of d
        zero_d_kernel<<<BATCH * NP / 256, 256>>>(dcol);
        softmax_rows<<<dim3(NP, BATCH), 256>>>(energy, Pb, dcol);
        rcp_d_kernel<<<BATCH * NP / 256, 256>>>(dcol, dinv);
        // xv = v_w @ h + v_b -> plain bf16
        gemm_bf16<256, 2048, 768, 128, 128, false, M_XV, true, true>
            <<<dim3(16, 2, BATCH), 256, SMEM_BIG>>>(wA + (size_t)(768 + i*256) * 512, 0,
                                          hBcur, sB2,
                                          nullptr, 0, sa_v_b + (size_t)i * C, nullptr,
                                          nullptr, nullptr, xv, sHN);
        // u = h - (xv @ P)*inv_d -> uB split (pure bf16 GEMM, K=2048)
        gemm_bf16<256, 2048, 2048, 128, 128, false, M_XR, false, false>
            <<<dim3(16, 2, BATCH), 256, SMEM_BIG>>>(xv, sHN, Pb, sP,
                                          nullptr, 0, hcur, dinv, nullptr, nullptr,
                                          uB, sB2);
        // h_next = h + relu(bn(t_w @ u)); out slice + fp32 hnxt + split hBnxt
        gemm_bf16<256, 2048, 768, 128, 128, false, M_TOUT, true, true>
            <<<dim3(16, 2, BATCH), 256, SMEM_BIG>>>(wA + (size_t)(1792 + i*256) * 512, 0,
                                          uB, sB2,
                                          hnxt, sHN, bnp + (4+i)*C, bnp + (8+i)*C, hcur,
                                          out + (size_t)i * C * NP,
                                          hBnxt, sB2);
        float* tf = hcur; hcur = hnxt; hnxt = tf;
        bf16* tb = hBcur; hBcur = hBnxt; hBnxt = tb;
    }
    (void)in_sizes; (void)n_in; (void)out_size;
}

// round 14
// speedup vs baseline: 1.3940x; 1.3659x over previous
#include <cuda_runtime.h>
#include <cuda_bf16.h>
#include <cuda_fp16.h>
#include <cstdint>
#include <cstddef>

using bf16 = __nv_bfloat16;

constexpr int BATCH = 16;
constexpr int C     = 256;
constexpr int NP    = 2048;
constexpr int CQ    = 64;
constexpr float EPSBN = 1e-3f;

// ---------------- scratch (static device buffers; no allocation) -------------
__device__ float  g_h0[BATCH * C * NP];
__device__ float  g_h1[BATCH * C * NP];
__device__ __half g_energy[(size_t)BATCH * NP * NP];            // 134 MB
__device__ bf16   g_P     [(size_t)BATCH * NP * NP];            // 134 MB
__device__ bf16   g_xB [(size_t)BATCH * 2 * C * NP];            // [hi;lo]
__device__ bf16   g_hB0[(size_t)BATCH * 2 * C * NP];
__device__ bf16   g_hB1[(size_t)BATCH * 2 * C * NP];
__device__ bf16   g_q  [(size_t)BATCH * 2 * CQ * NP];           // [hi;lo]
__device__ bf16   g_xv [(size_t)BATCH * C * NP];                // plain bf16
__device__ bf16   g_uB [(size_t)BATCH * 2 * C * NP];
__device__ float  g_d  [BATCH * NP];
__device__ float  g_dinv[BATCH * NP];
__device__ float  g_bnp[12 * C];
// weight splits [hi(256)|lo(256)]: rows: conv1 0..255, conv2 256..511, qk 512..767,
// v 768..1791, t 1792..2815
__device__ bf16   g_wA [(size_t)2816 * 512];

// ---------------- BN prefold -------------------------------------------------
__global__ void bn_prep(const float* g1, const float* b1, const float* m1, const float* v1,
                        const float* g2, const float* b2, const float* m2, const float* v2,
                        const float* sg, const float* sb, const float* sm, const float* sv,
                        const float* stb)
{
    int c = threadIdx.x;
    int w = blockIdx.x;
    if (w == 0) {
        float a = g1[c] * rsqrtf(v1[c] + EPSBN);
        g_bnp[c] = a; g_bnp[C + c] = b1[c] - m1[c] * a;
    } else if (w == 1) {
        float a = g2[c] * rsqrtf(v2[c] + EPSBN);
        g_bnp[2*C + c] = a; g_bnp[3*C + c] = b2[c] - m2[c] * a;
    } else {
        int i = w - 2;
        float a = sg[i*C + c] * rsqrtf(sv[i*C + c] + EPSBN);
        g_bnp[(4+i)*C + c] = a;
        g_bnp[(8+i)*C + c] = sb[i*C + c] - sm[i*C + c] * a + a * stb[i*C + c];
    }
}

// ---------------- split helpers ---------------------------------------------
__device__ __forceinline__ void split2(float v, bf16& hi, bf16& lo)
{
    hi = __float2bfloat16(v);
    lo = __float2bfloat16(v - __bfloat162float(hi));
}

// ALL weights in one launch: rows 0..255 conv1, 256..511 conv2, 512..767 qk,
// 768..1791 v, 1792..2815 t.
__global__ void wsplit_all(const float* __restrict__ c1, const float* __restrict__ c2,
                           const float* __restrict__ qk, const float* __restrict__ vw,
                           const float* __restrict__ tw)
{
    int idx = blockIdx.x * 256 + threadIdx.x;   // 0 .. 2816*256-1
    int row = idx >> 8, k = idx & 255;
    const float* src;
    int r;
    if (row < 256)       { src = c1; r = row; }
    else if (row < 512)  { src = c2; r = row - 256; }
    else if (row < 768)  { src = qk; r = row - 512; }
    else if (row < 1792) { src = vw; r = row - 768; }
    else                 { src = tw; r = row - 1792; }
    bf16 hi, lo; split2(src[r * 256 + k], hi, lo);
    bf16* d = g_wA + (size_t)row * 512;
    d[k] = hi; d[256 + k] = lo;
}

// x: src fp32 [B,C,NP] -> dst bf16 [B,2C,NP] = [hi;lo]
__global__ void xsplitB(const float* __restrict__ src, bf16* __restrict__ dst)
{
    size_t idx = (size_t)blockIdx.x * 256 + threadIdx.x;
    int b = (int)(idx / ((size_t)C * NP));
    size_t rem = idx - (size_t)b * C * NP;
    bf16 hi, lo; split2(src[idx], hi, lo);
    bf16* d = dst + (size_t)b * 2 * C * NP;
    d[rem] = hi; d[(size_t)C * NP + rem] = lo;
}

// ---------------- mma.sync bf16 GEMM with fused epilogues --------------------
enum { M_CONV1 = 0, M_CONV2, M_Q, M_ENERGY, M_XV, M_XR, M_TOUT };

__device__ __forceinline__ void ldm_x4(uint32_t* r, uint32_t a)
{
    asm volatile("ldmatrix.sync.aligned.m8n8.x4.shared.b16 {%0,%1,%2,%3}, [%4];"
                 : "=r"(r[0]), "=r"(r[1]), "=r"(r[2]), "=r"(r[3]) : "r"(a));
}
__device__ __forceinline__ void ldm_x4_t(uint32_t* r, uint32_t a)
{
    asm volatile("ldmatrix.sync.aligned.m8n8.x4.trans.shared.b16 {%0,%1,%2,%3}, [%4];"
                 : "=r"(r[0]), "=r"(r[1]), "=r"(r[2]), "=r"(r[3]) : "r"(a));
}
__device__ __forceinline__ void cpa16(uint32_t s, const void* g)
{
    asm volatile("cp.async.cg.shared.global [%0], [%1], 16;" :: "r"(s), "l"(g));
}
__device__ __forceinline__ void mma_bf16(float* c, const uint32_t* a, const uint32_t* b)
{
    asm volatile("mma.sync.aligned.m16n8k16.row.col.f32.bf16.bf16.f32 "
                 "{%0,%1,%2,%3}, {%4,%5,%6,%7}, {%8,%9}, {%0,%1,%2,%3};"
                 : "+f"(c[0]), "+f"(c[1]), "+f"(c[2]), "+f"(c[3])
                 : "r"(a[0]), "r"(a[1]), "r"(a[2]), "r"(a[3]), "r"(b[0]), "r"(b[1]));
}

// MAPA: A logical k-thirds [hi|lo|hi] stored [hi|lo]  (phys K = 2*K3/3)
// MAPB: B logical k-thirds [hi;hi;lo] stored [hi;lo]
// SYM:  symmetric NxN product (energy); off-diagonal tiles mirrored via smem.
// BK=64, 2-stage, wait_group 0 — validated optimum.
template<int M, int N, int K3, int BM, int BN, bool ATRANS, int MODE,
         bool MAPA, bool MAPB, bool SYM = false>
__global__ void __launch_bounds__(256, 2)
gemm_bf16(const bf16* __restrict__ A, size_t sA,
          const bf16* __restrict__ B, size_t sB,
          float* __restrict__ Cp, size_t sC,
          const float* __restrict__ e1, const float* __restrict__ e2,
          const float* __restrict__ e3, float* __restrict__ out2,
          bf16* __restrict__ sp1, size_t sSp1)
{
    constexpr int BK = 64;
    constexpr int KB = K3 / BK;
    constexpr int T3 = K3 / 3;
    constexpr int WM = BM / 2, WN = BN / 4;
    constexpr int MT = WM / 16, NT = WN / 8;
    constexpr int A_STAGE = BM * BK * 2;      // bytes
    constexpr int B_STAGE = BK * BN * 2;
    constexpr int STAGE   = A_STAGE + B_STAGE;
    constexpr int CPRA = BK / 8;              // 16B chunks per A row (non-trans)
    constexpr int LDA = ATRANS ? M : (MAPA ? 2 * T3 : K3);

    extern __shared__ __align__(16) uint8_t smem[];
    const uint32_t s0 = (uint32_t)__cvta_generic_to_shared(smem);

    const int tid  = threadIdx.x;
    const int lane = tid & 31;
    const int w    = tid >> 5;
    const int wm   = w >> 2, wn = w & 3;
    const int b    = blockIdx.z;

    int bxv = 0, byv = 0, m0, n0;
    if (SYM) {
        int t = blockIdx.x;
        bxv = (int)floorf((sqrtf(8.0f * t + 1.0f) - 1.0f) * 0.5f);
        while ((bxv + 1) * (bxv + 2) / 2 <= t) ++bxv;
        while (bxv * (bxv + 1) / 2 > t) --bxv;
        byv = t - bxv * (bxv + 1) / 2;
        m0 = byv * BM;
        n0 = bxv * BN;
    } else {
        m0 = blockIdx.y * BM;
        n0 = blockIdx.x * BN;
    }

    const bf16* Ab = A + (size_t)b * sA;
    const bf16* Bb = B + (size_t)b * sB;

    float acc[MT][NT][4];
    #pragma unroll
    for (int i = 0; i < MT; i++)
        #pragma unroll
        for (int j = 0; j < NT; j++)
            #pragma unroll
            for (int q = 0; q < 4; q++) acc[i][j][q] = 0.f;

    auto issue = [&](int kb, int stage) {
        const int k0 = kb * BK;
        const int k0A = MAPA ? (k0 < 2 * T3 ? k0 : k0 - 2 * T3) : k0;
        const int k0B = MAPB ? (k0 < T3 ? k0 : k0 - T3) : k0;  // [hi;hi;lo]->[hi;lo]
        const uint32_t sAst = s0 + stage * STAGE;
        const uint32_t sBst = sAst + A_STAGE;
        if (ATRANS) {
            constexpr int CH = BK * BM / 8;   // 16B chunks
            #pragma unroll
            for (int i = 0; i < CH / 256; i++) {
                int c = tid + i * 256;
                int r = c / (BM / 8), ch = c % (BM / 8);
                const bf16* g = Ab + (size_t)(k0A + r) * LDA + m0 + ch * 8;
                uint32_t s = sAst + r * (BM * 2) + ((ch ^ (r & 7)) << 4);
                cpa16(s, g);
            }
        } else {
            constexpr int CH = BM * BK / 8;
            #pragma unroll
            for (int i = 0; i < CH / 256; i++) {
                int c = tid + i * 256;
                int r = c / CPRA, ch = c % CPRA;
                const bf16* g = Ab + (size_t)(m0 + r) * LDA + k0A + ch * 8;
                uint32_t s = sAst + r * (BK * 2) + ((ch ^ (r & (CPRA - 1))) << 4);
                cpa16(s, g);
            }
        }
        {
            constexpr int CH = BK * BN / 8;
            #pragma unroll
            for (int i = 0; i < CH / 256; i++) {
                int c = tid + i * 256;
                int r = c / (BN / 8), ch = c % (BN / 8);
                const bf16* g = Bb + (size_t)(k0B + r) * N + n0 + ch * 8;
                uint32_t s = sBst + r * (BN * 2) + ((ch ^ (r & 7)) << 4);
                cpa16(s, g);
            }
        }
        asm volatile("cp.async.commit_group;");
    };

    auto compute = [&](int stage) {
        const uint32_t sAst = s0 + stage * STAGE;
        const uint32_t sBst = sAst + A_STAGE;
        #pragma unroll
        for (int ks = 0; ks < BK / 16; ks++) {
            uint32_t afr[MT][4];
            uint32_t bfr[NT][2];
            #pragma unroll
            for (int mt = 0; mt < MT; mt++) {
                if (!ATRANS) {
                    int r  = wm * WM + mt * 16 + (lane & 15);
                    int ch = 2 * ks + (lane >> 4);
                    uint32_t a = sAst + r * (BK * 2) + ((ch ^ (r & (CPRA - 1))) << 4);
                    ldm_x4(afr[mt], a);
                } else {
                    int k  = 16 * ks + (lane & 7) + ((lane >> 4) << 3);
                    int mo = wm * WM + mt * 16 + (((lane >> 3) & 1) << 3);
                    int ch = mo >> 3;
                    uint32_t a = sAst + k * (BM * 2) + ((ch ^ (k & 7)) << 4);
                    ldm_x4_t(afr[mt], a);
                }
            }
            #pragma unroll
            for (int p = 0; p < NT / 2; p++) {
                int k  = 16 * ks + (lane & 15);
                int ch = (wn * WN + p * 16) / 8 + (lane >> 4);
                uint32_t a = sBst + k * (BN * 2) + ((ch ^ (k & 7)) << 4);
                uint32_t r4[4];
                ldm_x4_t(r4, a);
                bfr[2*p][0] = r4[0]; bfr[2*p][1] = r4[1];
                bfr[2*p+1][0] = r4[2]; bfr[2*p+1][1] = r4[3];
            }
            #pragma unroll
            for (int mt = 0; mt < MT; mt++)
                #pragma unroll
                for (int nt = 0; nt < NT; nt++)
                    mma_bf16(acc[mt][nt], afr[mt], bfr[nt]);
        }
    };

    issue(0, 0);
    for (int kb = 0; kb < KB; kb++) {
        asm volatile("cp.async.wait_group 0;");
        __syncthreads();
        if (kb + 1 < KB) issue(kb + 1, (kb + 1) & 1);
        compute(kb & 1);
    }

    // ----------------------- epilogue -----------------------
    float*  Cb  = (MODE == M_CONV2 || MODE == M_TOUT) ? Cp + (size_t)b * sC : nullptr;
    __half* CbH = (MODE == M_ENERGY) ? (__half*)Cp + (size_t)b * sC : nullptr;
    const int er = lane >> 2;
    const int ec = (lane & 3) * 2;

    const bool mirror = SYM && (bxv != byv);
    __half* st = reinterpret_cast<__half*>(smem);   // 128x(128+2) tile
    if (mirror) __syncthreads();   // stages done; reuse smem for transpose

    #pragma unroll
    for (int mt = 0; mt < MT; mt++) {
        #pragma unroll
        for (int half = 0; half < 2; half++) {
            const int lm = wm * WM + mt * 16 + er + half * 8;
            const int gm = m0 + lm;
            float alpha = 0.f, beta = 0.f;
            if (MODE == M_CONV1 || MODE == M_CONV2 || MODE == M_TOUT) {
                alpha = e1[gm]; beta = e2[gm];
            } else if (MODE == M_XV) {
                alpha = e1[gm];
            }
            #pragma unroll
            for (int nt = 0; nt < NT; nt++) {
                const int ln = wn * WN + nt * 8 + ec;
                const int gn = n0 + ln;
                float s0v = acc[mt][nt][half * 2 + 0];
                float s1v = acc[mt][nt][half * 2 + 1];
                float r0, r1;

                if (MODE == M_CONV1 || MODE == M_CONV2) {
                    r0 = fmaxf(fmaf(alpha, s0v, beta), 0.f);
                    r1 = fmaxf(fmaf(alpha, s1v, beta), 0.f);
                } else if (MODE == M_Q || MODE == M_ENERGY) {
                    r0 = s0v; r1 = s1v;
                } else if (MODE == M_XV) {
                    r0 = s0v + alpha; r1 = s1v + alpha;
                } else if (MODE == M_XR) {
                    // e2 = precomputed 1/(1e-9+d): multiply instead of divide
                    float i0 = e2[(size_t)b * NP + gn];
                    float i1 = e2[(size_t)b * NP + gn + 1];
                    float h0 = e1[(size_t)b * M * N + (size_t)gm * N + gn];
                    float h1 = e1[(size_t)b * M * N + (size_t)gm * N + gn + 1];
                    r0 = fmaf(-s0v, i0, h0);
                    r1 = fmaf(-s1v, i1, h1);
                } else { // M_TOUT
                    float t0 = fmaxf(fmaf(alpha, s0v, beta), 0.f);
                    float t1 = fmaxf(fmaf(alpha, s1v, beta), 0.f);
                    r0 = e3[(size_t)b * M * N + (size_t)gm * N + gn] + t0;
                    r1 = e3[(size_t)b * M * N + (size_t)gm * N + gn + 1] + t1;
                }

                if (MODE == M_ENERGY) {
                    __half2 hv = __floats2half2_rn(r0, r1);
                    *(__half2*)&CbH[(size_t)gm * N + gn] = hv;
                    if (mirror) {
                        st[lm * (BN + 2) + ln]     = __low2half(hv);
                        st[lm * (BN + 2) + ln + 1] = __high2half(hv);
                    }
                }
                if (MODE == M_CONV2 || MODE == M_TOUT) {
                    float2 v; v.x = r0; v.y = r1;
                    *(float2*)&Cb[(size_t)gm * N + gn] = v;
                }
                if (MODE == M_TOUT) {
                    float2 v; v.x = r0; v.y = r1;
                    *(float2*)&out2[(size_t)b * 4 * M * N + (size_t)gm * N + gn] = v;
                }

                if (MODE == M_XV) {
                    __nv_bfloat162 hh;
                    hh.x = __float2bfloat16(r0); hh.y = __float2bfloat16(r1);
                    bf16* d = sp1 + (size_t)b * sSp1;
                    *(__nv_bfloat162*)&d[(size_t)gm * N + gn] = hh;
                } else if (MODE == M_CONV1 || MODE == M_CONV2 ||
                           MODE == M_XR || MODE == M_TOUT || MODE == M_Q) {
                    // canonical split [hi;lo]
                    bf16 h0b, l0b, h1b, l1b;
                    split2(r0, h0b, l0b); split2(r1, h1b, l1b);
                    __nv_bfloat162 hh; hh.x = h0b; hh.y = h1b;
                    __nv_bfloat162 ll; ll.x = l0b; ll.y = l1b;
                    bf16* d = sp1 + (size_t)b * sSp1;
                    *(__nv_bfloat162*)&d[(size_t)gm * N + gn] = hh;
                    *(__nv_bfloat162*)&d[(size_t)(M + gm) * N + gn] = ll;
                }
            }
        }
    }

    if (MODE == M_ENERGY && mirror) {
        __syncthreads();
        // write transposed tile: rows [n0, n0+BN), cols [m0, m0+BM)
        #pragma unroll
        for (int pass = 0; pass < (BM * BN) / (256 * 8); pass++) {
            int idx = pass * 256 + tid;
            int j = idx >> 4;            // transposed row 0..127
            int cchunk = (idx & 15) * 8; // col chunk
            __half tmp[8];
            #pragma unroll
            for (int k = 0; k < 8; k++) tmp[k] = st[(cchunk + k) * (BN + 2) + j];
            *(uint4*)&CbH[(size_t)(n0 + j) * N + m0 + cchunk] = *(uint4*)tmp;
        }
    }
}

// smem sizes (BK=64, 2 stages)
constexpr int SMEM_BIG = 2 * (128 * 64 * 2 + 64 * 128 * 2);   // 64 KB
constexpr int SMEM_Q   = 2 * (64 * 64 * 2 + 64 * 128 * 2);    // 48 KB

// ------- row softmax: fp16 energy in, bf16 P out (NO atomics — R13) ----------
__global__ void __launch_bounds__(256) softmax_rows(const __half* __restrict__ E,
                                                    bf16* __restrict__ P)
{
    const int tid = threadIdx.x;
    const int row = blockIdx.x;
    const int b   = blockIdx.y;
    const __half* p = E + ((size_t)b * NP + row) * NP;

    float v[8];
    float mx = -3.4e38f;
    #pragma unroll
    for (int k = 0; k < 8; k++) { v[k] = __half2float(p[tid + k*256]); mx = fmaxf(mx, v[k]); }

    #pragma unroll
    for (int o = 16; o > 0; o >>= 1) mx = fmaxf(mx, __shfl_xor_sync(0xffffffffu, mx, o));
    __shared__ float red[8];
    if ((tid & 31) == 0) red[tid >> 5] = mx;
    __syncthreads();
    mx = red[0];
    #pragma unroll
    for (int w = 1; w < 8; w++) mx = fmaxf(mx, red[w]);

    float s = 0.f;
    #pragma unroll
    for (int k = 0; k < 8; k++) { v[k] = __expf(v[k] - mx); s += v[k]; }
    #pragma unroll
    for (int o = 16; o > 0; o >>= 1) s += __shfl_xor_sync(0xffffffffu, s, o);
    __syncthreads();
    if ((tid & 31) == 0) red[tid >> 5] = s;
    __syncthreads();
    s = red[0];
    #pragma unroll
    for (int w = 1; w < 8; w++) s += red[w];

    const float inv = 1.f / s;
    bf16* po = P + ((size_t)b * NP + row) * NP;
    #pragma unroll
    for (int k = 0; k < 8; k++) {
        int n = tid + k * 256;
        po[n] = __float2bfloat16(v[k] * inv);
    }
}

// column sums of bf16 P: coalesced row-major reads, 8 partial atomics/address
__global__ void __launch_bounds__(256) colsum_kernel(const bf16* __restrict__ P,
                                                     float* __restrict__ d)
{
    const int b = blockIdx.z;
    const int m = blockIdx.x * 256 + threadIdx.x;
    const int n0 = blockIdx.y * (NP / 8);
    const bf16* pb = P + (size_t)b * NP * NP;
    float s = 0.f;
    #pragma unroll 4
    for (int n = n0; n < n0 + NP / 8; n++)
        s += __bfloat162float(pb[(size_t)n * NP + m]);
    atomicAdd(&d[b * NP + m], s);
}

__global__ void zero_d_kernel(float* d) { d[blockIdx.x * 256 + threadIdx.x] = 0.f; }

// inv_d = 1/(1e-9 + d), so XR epilogue multiplies instead of dividing
__global__ void rcp_d_kernel(const float* __restrict__ d, float* __restrict__ dinv)
{
    int i = blockIdx.x * 256 + threadIdx.x;
    dinv[i] = __frcp_rn(1e-9f + d[i]);
}

// ---------------- launch -----------------------------------------------------
extern "C" void kernel_launch(void* const* d_in, const int* in_sizes, int n_in,
                              void* d_out, int out_size)
{
    const float* x       = (const float*)d_in[0];
    const float* conv1_w = (const float*)d_in[1];
    const float* conv2_w = (const float*)d_in[2];
    const float* bn1_g = (const float*)d_in[3];
    const float* bn1_b = (const float*)d_in[4];
    const float* bn1_m = (const float*)d_in[5];
    const float* bn1_v = (const float*)d_in[6];
    const float* bn2_g = (const float*)d_in[7];
    const float* bn2_b = (const float*)d_in[8];
    const float* bn2_m = (const float*)d_in[9];
    const float* bn2_v = (const float*)d_in[10];
    const float* sa_qk_w = (const float*)d_in[11];
    const float* sa_v_w  = (const float*)d_in[12];
    const float* sa_v_b  = (const float*)d_in[13];
    const float* sa_t_w  = (const float*)d_in[14];
    const float* sa_t_b  = (const float*)d_in[15];
    const float* sa_g    = (const float*)d_in[16];
    const float* sa_b    = (const float*)d_in[17];
    const float* sa_m    = (const float*)d_in[18];
    const float* sa_var  = (const float*)d_in[19];
    float* out = (float*)d_out;

    float *h0, *h1, *dcol, *dinv, *bnp;
    __half* energy;
    bf16 *xB, *hB0, *hB1, *qbuf, *Pb, *xv, *uB, *wA;
    cudaGetSymbolAddress((void**)&h0,     g_h0);
    cudaGetSymbolAddress((void**)&h1,     g_h1);
    cudaGetSymbolAddress((void**)&energy, g_energy);
    cudaGetSymbolAddress((void**)&dcol,   g_d);
    cudaGetSymbolAddress((void**)&dinv,   g_dinv);
    cudaGetSymbolAddress((void**)&bnp,    g_bnp);
    cudaGetSymbolAddress((void**)&xB,     g_xB);
    cudaGetSymbolAddress((void**)&hB0,    g_hB0);
    cudaGetSymbolAddress((void**)&hB1,    g_hB1);
    cudaGetSymbolAddress((void**)&qbuf,   g_q);
    cudaGetSymbolAddress((void**)&Pb,     g_P);
    cudaGetSymbolAddress((void**)&xv,     g_xv);
    cudaGetSymbolAddress((void**)&uB,     g_uB);
    cudaGetSymbolAddress((void**)&wA,     g_wA);

    const size_t sB2 = (size_t)2 * C * NP;     // [hi;lo] B-form stride (512x2048)
    const size_t sQ2 = (size_t)2 * CQ * NP;    // q split stride (128x2048)
    const size_t sP  = (size_t)NP * NP;
    const size_t sHN = (size_t)C * NP;

    // opt in to >48KB dynamic smem (immediate driver calls; not graph-captured)
    cudaFuncSetAttribute(gemm_bf16<256, 2048, 768, 128, 128, false, M_CONV1, true, true>,
                         cudaFuncAttributeMaxDynamicSharedMemorySize, SMEM_BIG);
    cudaFuncSetAttribute(gemm_bf16<256, 2048, 768, 128, 128, false, M_CONV2, true, true>,
                         cudaFuncAttributeMaxDynamicSharedMemorySize, SMEM_BIG);
    cudaFuncSetAttribute(gemm_bf16<64, 2048, 768, 64, 128, false, M_Q, true, true>,
                         cudaFuncAttributeMaxDynamicSharedMemorySize, SMEM_Q);
    cudaFuncSetAttribute(gemm_bf16<2048, 2048, 192, 128, 128, true, M_ENERGY, true, true, true>,
                         cudaFuncAttributeMaxDynamicSharedMemorySize, SMEM_BIG);
    cudaFuncSetAttribute(gemm_bf16<256, 2048, 768, 128, 128, false, M_XV, true, true>,
                         cudaFuncAttributeMaxDynamicSharedMemorySize, SMEM_BIG);
    cudaFuncSetAttribute(gemm_bf16<256, 2048, 2048, 128, 128, false, M_XR, false, false>,
                         cudaFuncAttributeMaxDynamicSharedMemorySize, SMEM_BIG);
    cudaFuncSetAttribute(gemm_bf16<256, 2048, 768, 128, 128, false, M_TOUT, true, true>,
                         cudaFuncAttributeMaxDynamicSharedMemorySize, SMEM_BIG);

    bn_prep<<<6, 256>>>(bn1_g, bn1_b, bn1_m, bn1_v,
                        bn2_g, bn2_b, bn2_m, bn2_v,
                        sa_g, sa_b, sa_m, sa_var, sa_t_b);

    wsplit_all<<<2816, 256>>>(conv1_w, conv2_w, sa_qk_w, sa_v_w, sa_t_w);

    xsplitB<<<(BATCH * C * NP) / 256, 256>>>(x, xB);

    // conv1: split-only -> hB0
    gemm_bf16<256, 2048, 768, 128, 128, false, M_CONV1, true, true>
        <<<dim3(16, 2, BATCH), 256, SMEM_BIG>>>(wA + (size_t)0 * 512, 0, xB, sB2,
                                      nullptr, 0, bnp + 0, bnp + C, nullptr, nullptr,
                                      hB0, sB2);
    // conv2: fp32 h0 + split hB1
    gemm_bf16<256, 2048, 768, 128, 128, false, M_CONV2, true, true>
        <<<dim3(16, 2, BATCH), 256, SMEM_BIG>>>(wA + (size_t)256 * 512, 0, hB0, sB2,
                                      h0, sHN, bnp + 2*C, bnp + 3*C, nullptr, nullptr,
                                      hB1, sB2);

    float* hcur = h0;
    float* hnxt = h1;
    bf16* hBcur = hB1;
    bf16* hBnxt = hB0;
    for (int i = 0; i < 4; i++) {
        // q (split [hi;lo]) -> qbuf   (contract over C=256 -> K3=768)
        gemm_bf16<64, 2048, 768, 64, 128, false, M_Q, true, true>
            <<<dim3(16, 1, BATCH), 256, SMEM_Q>>>(wA + (size_t)(512 + i*64) * 512, 0,
                                          hBcur, sB2,
                                          nullptr, 0, nullptr, nullptr, nullptr, nullptr,
                                          qbuf, sQ2);
        // energy = q^T q, symmetric: only upper-triangle block pairs (136 of 256)
        gemm_bf16<2048, 2048, 192, 128, 128, true, M_ENERGY, true, true, true>
            <<<dim3(136, 1, BATCH), 256, SMEM_BIG>>>(qbuf, sQ2, qbuf, sQ2,
                                           (float*)energy, sP, nullptr, nullptr, nullptr,
                                           nullptr, nullptr, 0);
        // softmax (no atomics), then separate coalesced column-sum, then 1/d
        softmax_rows<<<dim3(NP, BATCH), 256>>>(energy, Pb);
        zero_d_kernel<<<BATCH * NP / 256, 256>>>(dcol);
        colsum_kernel<<<dim3(NP / 256, 8, BATCH), 256>>>(Pb, dcol);
        rcp_d_kernel<<<BATCH * NP / 256, 256>>>(dcol, dinv);
        // xv = v_w @ h + v_b -> plain bf16
        gemm_bf16<256, 2048, 768, 128, 128, false, M_XV, true, true>
            <<<dim3(16, 2, BATCH), 256, SMEM_BIG>>>(wA + (size_t)(768 + i*256) * 512, 0,
                                          hBcur, sB2,
                                          nullptr, 0, sa_v_b + (size_t)i * C, nullptr,
                                          nullptr, nullptr, xv, sHN);
        // u = h - (xv @ P)*inv_d -> uB split (pure bf16 GEMM, K=2048)
        gemm_bf16<256, 2048, 2048, 128, 128, false, M_XR, false, false>
            <<<dim3(16, 2, BATCH), 256, SMEM_BIG>>>(xv, sHN, Pb, sP,
                                          nullptr, 0, hcur, dinv, nullptr, nullptr,
                                          uB, sB2);
        // h_next = h + relu(bn(t_w @ u)); out slice + fp32 hnxt + split hBnxt
        gemm_bf16<256, 2048, 768, 128, 128, false, M_TOUT, true, true>
            <<<dim3(16, 2, BATCH), 256, SMEM_BIG>>>(wA + (size_t)(1792 + i*256) * 512, 0,
                                          uB, sB2,
                                          hnxt, sHN, bnp + (4+i)*C, bnp + (8+i)*C, hcur,
                                          out + (size_t)i * C * NP,
                                          hBnxt, sB2);
        float* tf = hcur; hcur = hnxt; hnxt = tf;
        bf16* tb = hBcur; hBcur = hBnxt; hBnxt = tb;
    }
    (void)in_sizes; (void)n_in; (void)out_size;
}

// round 15
// speedup vs baseline: 1.4177x; 1.0171x over previous
#include <cuda_runtime.h>
#include <cuda_bf16.h>
#include <cuda_fp16.h>
#include <cstdint>
#include <cstddef>

using bf16 = __nv_bfloat16;

constexpr int BATCH = 16;
constexpr int C     = 256;
constexpr int NP    = 2048;
constexpr int CQ    = 64;
constexpr float EPSBN = 1e-3f;

// ---------------- scratch (static device buffers; no allocation) -------------
__device__ float  g_h0[BATCH * C * NP];
__device__ float  g_h1[BATCH * C * NP];
__device__ __half g_energy[(size_t)BATCH * NP * NP];            // 134 MB
__device__ bf16   g_P     [(size_t)BATCH * NP * NP];            // 134 MB
__device__ bf16   g_xB [(size_t)BATCH * 2 * C * NP];            // [hi;lo]
__device__ bf16   g_hB0[(size_t)BATCH * 2 * C * NP];
__device__ bf16   g_hB1[(size_t)BATCH * 2 * C * NP];
__device__ bf16   g_q  [(size_t)BATCH * 2 * CQ * NP];           // [hi;lo]
__device__ bf16   g_xv [(size_t)BATCH * C * NP];                // plain bf16
__device__ bf16   g_uB [(size_t)BATCH * 2 * C * NP];
__device__ float  g_d  [BATCH * NP];
__device__ float  g_dinv[BATCH * NP];
__device__ float  g_bnp[12 * C];
// weight splits [hi(256)|lo(256)]: rows: conv1 0..255, conv2 256..511, qk 512..767,
// v 768..1791, t 1792..2815
__device__ bf16   g_wA [(size_t)2816 * 512];

// ---------------- BN prefold -------------------------------------------------
__global__ void bn_prep(const float* g1, const float* b1, const float* m1, const float* v1,
                        const float* g2, const float* b2, const float* m2, const float* v2,
                        const float* sg, const float* sb, const float* sm, const float* sv,
                        const float* stb)
{
    int c = threadIdx.x;
    int w = blockIdx.x;
    if (w == 0) {
        float a = g1[c] * rsqrtf(v1[c] + EPSBN);
        g_bnp[c] = a; g_bnp[C + c] = b1[c] - m1[c] * a;
    } else if (w == 1) {
        float a = g2[c] * rsqrtf(v2[c] + EPSBN);
        g_bnp[2*C + c] = a; g_bnp[3*C + c] = b2[c] - m2[c] * a;
    } else {
        int i = w - 2;
        float a = sg[i*C + c] * rsqrtf(sv[i*C + c] + EPSBN);
        g_bnp[(4+i)*C + c] = a;
        g_bnp[(8+i)*C + c] = sb[i*C + c] - sm[i*C + c] * a + a * stb[i*C + c];
    }
}

// ---------------- split helpers ---------------------------------------------
__device__ __forceinline__ void split2(float v, bf16& hi, bf16& lo)
{
    hi = __float2bfloat16(v);
    lo = __float2bfloat16(v - __bfloat162float(hi));
}

// ALL weights in one launch: rows 0..255 conv1, 256..511 conv2, 512..767 qk,
// 768..1791 v, 1792..2815 t.
__global__ void wsplit_all(const float* __restrict__ c1, const float* __restrict__ c2,
                           const float* __restrict__ qk, const float* __restrict__ vw,
                           const float* __restrict__ tw)
{
    int idx = blockIdx.x * 256 + threadIdx.x;   // 0 .. 2816*256-1
    int row = idx >> 8, k = idx & 255;
    const float* src;
    int r;
    if (row < 256)       { src = c1; r = row; }
    else if (row < 512)  { src = c2; r = row - 256; }
    else if (row < 768)  { src = qk; r = row - 512; }
    else if (row < 1792) { src = vw; r = row - 768; }
    else                 { src = tw; r = row - 1792; }
    bf16 hi, lo; split2(src[r * 256 + k], hi, lo);
    bf16* d = g_wA + (size_t)row * 512;
    d[k] = hi; d[256 + k] = lo;
}

// x: src fp32 [B,C,NP] -> dst bf16 [B,2C,NP] = [hi;lo]
__global__ void xsplitB(const float* __restrict__ src, bf16* __restrict__ dst)
{
    size_t idx = (size_t)blockIdx.x * 256 + threadIdx.x;
    int b = (int)(idx / ((size_t)C * NP));
    size_t rem = idx - (size_t)b * C * NP;
    bf16 hi, lo; split2(src[idx], hi, lo);
    bf16* d = dst + (size_t)b * 2 * C * NP;
    d[rem] = hi; d[(size_t)C * NP + rem] = lo;
}

// ---------------- mma.sync bf16 GEMM with fused epilogues --------------------
enum { M_CONV1 = 0, M_CONV2, M_Q, M_ENERGY, M_XV, M_XR, M_TOUT };

__device__ __forceinline__ void ldm_x4(uint32_t* r, uint32_t a)
{
    asm volatile("ldmatrix.sync.aligned.m8n8.x4.shared.b16 {%0,%1,%2,%3}, [%4];"
                 : "=r"(r[0]), "=r"(r[1]), "=r"(r[2]), "=r"(r[3]) : "r"(a));
}
__device__ __forceinline__ void ldm_x4_t(uint32_t* r, uint32_t a)
{
    asm volatile("ldmatrix.sync.aligned.m8n8.x4.trans.shared.b16 {%0,%1,%2,%3}, [%4];"
                 : "=r"(r[0]), "=r"(r[1]), "=r"(r[2]), "=r"(r[3]) : "r"(a));
}
__device__ __forceinline__ void cpa16(uint32_t s, const void* g)
{
    asm volatile("cp.async.cg.shared.global [%0], [%1], 16;" :: "r"(s), "l"(g));
}
__device__ __forceinline__ void mma_bf16(float* c, const uint32_t* a, const uint32_t* b)
{
    asm volatile("mma.sync.aligned.m16n8k16.row.col.f32.bf16.bf16.f32 "
                 "{%0,%1,%2,%3}, {%4,%5,%6,%7}, {%8,%9}, {%0,%1,%2,%3};"
                 : "+f"(c[0]), "+f"(c[1]), "+f"(c[2]), "+f"(c[3])
                 : "r"(a[0]), "r"(a[1]), "r"(a[2]), "r"(a[3]), "r"(b[0]), "r"(b[1]));
}

// MAPA:  A logical k-thirds [hi|lo|hi] stored [hi|lo]  (phys K = 2*K3/3)
// MAPB:  B logical k-thirds [hi;hi;lo] stored [hi;lo]
// MAPBH: B logical k-halves [hi;hi]    stored [hi;lo]  (2-term split, R14: XV)
// SYM:   symmetric NxN product (energy); off-diagonal tiles mirrored via smem.
// BK=64, 2-stage, wait_group 0 — validated optimum.
template<int M, int N, int K3, int BM, int BN, bool ATRANS, int MODE,
         bool MAPA, bool MAPB, bool SYM = false, bool MAPBH = false>
__global__ void __launch_bounds__(256, 2)
gemm_bf16(const bf16* __restrict__ A, size_t sA,
          const bf16* __restrict__ B, size_t sB,
          float* __restrict__ Cp, size_t sC,
          const float* __restrict__ e1, const float* __restrict__ e2,
          const float* __restrict__ e3, float* __restrict__ out2,
          bf16* __restrict__ sp1, size_t sSp1)
{
    constexpr int BK = 64;
    constexpr int KB = K3 / BK;
    constexpr int T3 = K3 / 3;
    constexpr int WM = BM / 2, WN = BN / 4;
    constexpr int MT = WM / 16, NT = WN / 8;
    constexpr int A_STAGE = BM * BK * 2;      // bytes
    constexpr int B_STAGE = BK * BN * 2;
    constexpr int STAGE   = A_STAGE + B_STAGE;
    constexpr int CPRA = BK / 8;              // 16B chunks per A row (non-trans)
    constexpr int LDA = ATRANS ? M : (MAPA ? 2 * T3 : K3);

    extern __shared__ __align__(16) uint8_t smem[];
    const uint32_t s0 = (uint32_t)__cvta_generic_to_shared(smem);

    const int tid  = threadIdx.x;
    const int lane = tid & 31;
    const int w    = tid >> 5;
    const int wm   = w >> 2, wn = w & 3;
    const int b    = blockIdx.z;

    int bxv = 0, byv = 0, m0, n0;
    if (SYM) {
        int t = blockIdx.x;
        bxv = (int)floorf((sqrtf(8.0f * t + 1.0f) - 1.0f) * 0.5f);
        while ((bxv + 1) * (bxv + 2) / 2 <= t) ++bxv;
        while (bxv * (bxv + 1) / 2 > t) --bxv;
        byv = t - bxv * (bxv + 1) / 2;
        m0 = byv * BM;
        n0 = bxv * BN;
    } else {
        m0 = blockIdx.y * BM;
        n0 = blockIdx.x * BN;
    }

    const bf16* Ab = A + (size_t)b * sA;
    const bf16* Bb = B + (size_t)b * sB;

    float acc[MT][NT][4];
    #pragma unroll
    for (int i = 0; i < MT; i++)
        #pragma unroll
        for (int j = 0; j < NT; j++)
            #pragma unroll
            for (int q = 0; q < 4; q++) acc[i][j][q] = 0.f;

    auto issue = [&](int kb, int stage) {
        const int k0 = kb * BK;
        const int k0A = MAPA ? (k0 < 2 * T3 ? k0 : k0 - 2 * T3) : k0;
        const int k0B = MAPBH ? (k0 < K3 / 2 ? k0 : k0 - K3 / 2)
                              : (MAPB ? (k0 < T3 ? k0 : k0 - T3) : k0);
        const uint32_t sAst = s0 + stage * STAGE;
        const uint32_t sBst = sAst + A_STAGE;
        if (ATRANS) {
            constexpr int CH = BK * BM / 8;   // 16B chunks
            #pragma unroll
            for (int i = 0; i < CH / 256; i++) {
                int c = tid + i * 256;
                int r = c / (BM / 8), ch = c % (BM / 8);
                const bf16* g = Ab + (size_t)(k0A + r) * LDA + m0 + ch * 8;
                uint32_t s = sAst + r * (BM * 2) + ((ch ^ (r & 7)) << 4);
                cpa16(s, g);
            }
        } else {
            constexpr int CH = BM * BK / 8;
            #pragma unroll
            for (int i = 0; i < CH / 256; i++) {
                int c = tid + i * 256;
                int r = c / CPRA, ch = c % CPRA;
                const bf16* g = Ab + (size_t)(m0 + r) * LDA + k0A + ch * 8;
                uint32_t s = sAst + r * (BK * 2) + ((ch ^ (r & (CPRA - 1))) << 4);
                cpa16(s, g);
            }
        }
        {
            constexpr int CH = BK * BN / 8;
            #pragma unroll
            for (int i = 0; i < CH / 256; i++) {
                int c = tid + i * 256;
                int r = c / (BN / 8), ch = c % (BN / 8);
                const bf16* g = Bb + (size_t)(k0B + r) * N + n0 + ch * 8;
                uint32_t s = sBst + r * (BN * 2) + ((ch ^ (r & 7)) << 4);
                cpa16(s, g);
            }
        }
        asm volatile("cp.async.commit_group;");
    };

    auto compute = [&](int stage) {
        const uint32_t sAst = s0 + stage * STAGE;
        const uint32_t sBst = sAst + A_STAGE;
        #pragma unroll
        for (int ks = 0; ks < BK / 16; ks++) {
            uint32_t afr[MT][4];
            uint32_t bfr[NT][2];
            #pragma unroll
            for (int mt = 0; mt < MT; mt++) {
                if (!ATRANS) {
                    int r  = wm * WM + mt * 16 + (lane & 15);
                    int ch = 2 * ks + (lane >> 4);
                    uint32_t a = sAst + r * (BK * 2) + ((ch ^ (r & (CPRA - 1))) << 4);
                    ldm_x4(afr[mt], a);
                } else {
                    int k  = 16 * ks + (lane & 7) + ((lane >> 4) << 3);
                    int mo = wm * WM + mt * 16 + (((lane >> 3) & 1) << 3);
                    int ch = mo >> 3;
                    uint32_t a = sAst + k * (BM * 2) + ((ch ^ (k & 7)) << 4);
                    ldm_x4_t(afr[mt], a);
                }
            }
            #pragma unroll
            for (int p = 0; p < NT / 2; p++) {
                int k  = 16 * ks + (lane & 15);
                int ch = (wn * WN + p * 16) / 8 + (lane >> 4);
                uint32_t a = sBst + k * (BN * 2) + ((ch ^ (k & 7)) << 4);
                uint32_t r4[4];
                ldm_x4_t(r4, a);
                bfr[2*p][0] = r4[0]; bfr[2*p][1] = r4[1];
                bfr[2*p+1][0] = r4[2]; bfr[2*p+1][1] = r4[3];
            }
            #pragma unroll
            for (int mt = 0; mt < MT; mt++)
                #pragma unroll
                for (int nt = 0; nt < NT; nt++)
                    mma_bf16(acc[mt][nt], afr[mt], bfr[nt]);
        }
    };

    issue(0, 0);
    for (int kb = 0; kb < KB; kb++) {
        asm volatile("cp.async.wait_group 0;");
        __syncthreads();
        if (kb + 1 < KB) issue(kb + 1, (kb + 1) & 1);
        compute(kb & 1);
    }

    // ----------------------- epilogue -----------------------
    float*  Cb  = (MODE == M_CONV2 || MODE == M_TOUT) ? Cp + (size_t)b * sC : nullptr;
    __half* CbH = (MODE == M_ENERGY) ? (__half*)Cp + (size_t)b * sC : nullptr;
    const int er = lane >> 2;
    const int ec = (lane & 3) * 2;

    const bool mirror = SYM && (bxv != byv);
    __half* st = reinterpret_cast<__half*>(smem);   // 128x(128+2) tile
    if (mirror) __syncthreads();   // stages done; reuse smem for transpose

    #pragma unroll
    for (int mt = 0; mt < MT; mt++) {
        #pragma unroll
        for (int half = 0; half < 2; half++) {
            const int lm = wm * WM + mt * 16 + er + half * 8;
            const int gm = m0 + lm;
            float alpha = 0.f, beta = 0.f;
            if (MODE == M_CONV1 || MODE == M_CONV2 || MODE == M_TOUT) {
                alpha = e1[gm]; beta = e2[gm];
            } else if (MODE == M_XV) {
                alpha = e1[gm];
            }
            #pragma unroll
            for (int nt = 0; nt < NT; nt++) {
                const int ln = wn * WN + nt * 8 + ec;
                const int gn = n0 + ln;
                float s0v = acc[mt][nt][half * 2 + 0];
                float s1v = acc[mt][nt][half * 2 + 1];
                float r0, r1;

                if (MODE == M_CONV1 || MODE == M_CONV2) {
                    r0 = fmaxf(fmaf(alpha, s0v, beta), 0.f);
                    r1 = fmaxf(fmaf(alpha, s1v, beta), 0.f);
                } else if (MODE == M_Q || MODE == M_ENERGY) {
                    r0 = s0v; r1 = s1v;
                } else if (MODE == M_XV) {
                    r0 = s0v + alpha; r1 = s1v + alpha;
                } else if (MODE == M_XR) {
                    // e2 = precomputed 1/(1e-9+d): multiply instead of divide
                    float i0 = e2[(size_t)b * NP + gn];
                    float i1 = e2[(size_t)b * NP + gn + 1];
                    float h0 = e1[(size_t)b * M * N + (size_t)gm * N + gn];
                    float h1 = e1[(size_t)b * M * N + (size_t)gm * N + gn + 1];
                    r0 = fmaf(-s0v, i0, h0);
                    r1 = fmaf(-s1v, i1, h1);
                } else { // M_TOUT
                    float t0 = fmaxf(fmaf(alpha, s0v, beta), 0.f);
                    float t1 = fmaxf(fmaf(alpha, s1v, beta), 0.f);
                    r0 = e3[(size_t)b * M * N + (size_t)gm * N + gn] + t0;
                    r1 = e3[(size_t)b * M * N + (size_t)gm * N + gn + 1] + t1;
                }

                if (MODE == M_ENERGY) {
                    __half2 hv = __floats2half2_rn(r0, r1);
                    *(__half2*)&CbH[(size_t)gm * N + gn] = hv;
                    if (mirror) {
                        st[lm * (BN + 2) + ln]     = __low2half(hv);
                        st[lm * (BN + 2) + ln + 1] = __high2half(hv);
                    }
                }
                if (MODE == M_CONV2 || MODE == M_TOUT) {
                    float2 v; v.x = r0; v.y = r1;
                    *(float2*)&Cb[(size_t)gm * N + gn] = v;
                }
                if (MODE == M_TOUT) {
                    float2 v; v.x = r0; v.y = r1;
                    *(float2*)&out2[(size_t)b * 4 * M * N + (size_t)gm * N + gn] = v;
                }

                if (MODE == M_XV) {
                    __nv_bfloat162 hh;
                    hh.x = __float2bfloat16(r0); hh.y = __float2bfloat16(r1);
                    bf16* d = sp1 + (size_t)b * sSp1;
                    *(__nv_bfloat162*)&d[(size_t)gm * N + gn] = hh;
                } else if (MODE == M_CONV1 || MODE == M_CONV2 ||
                           MODE == M_XR || MODE == M_TOUT || MODE == M_Q) {
                    // canonical split [hi;lo]
                    bf16 h0b, l0b, h1b, l1b;
                    split2(r0, h0b, l0b); split2(r1, h1b, l1b);
                    __nv_bfloat162 hh; hh.x = h0b; hh.y = h1b;
                    __nv_bfloat162 ll; ll.x = l0b; ll.y = l1b;
                    bf16* d = sp1 + (size_t)b * sSp1;
                    *(__nv_bfloat162*)&d[(size_t)gm * N + gn] = hh;
                    *(__nv_bfloat162*)&d[(size_t)(M + gm) * N + gn] = ll;
                }
            }
        }
    }

    if (MODE == M_ENERGY && mirror) {
        __syncthreads();
        // write transposed tile: rows [n0, n0+BN), cols [m0, m0+BM)
        #pragma unroll
        for (int pass = 0; pass < (BM * BN) / (256 * 8); pass++) {
            int idx = pass * 256 + tid;
            int j = idx >> 4;            // transposed row 0..127
            int cchunk = (idx & 15) * 8; // col chunk
            __half tmp[8];
            #pragma unroll
            for (int k = 0; k < 8; k++) tmp[k] = st[(cchunk + k) * (BN + 2) + j];
            *(uint4*)&CbH[(size_t)(n0 + j) * N + m0 + cchunk] = *(uint4*)tmp;
        }
    }
}

// smem sizes (BK=64, 2 stages)
constexpr int SMEM_BIG = 2 * (128 * 64 * 2 + 64 * 128 * 2);   // 64 KB
constexpr int SMEM_Q   = 2 * (64 * 64 * 2 + 64 * 128 * 2);    // 48 KB

// ------- row softmax: fp16 energy in, bf16 P out (NO atomics) ----------------
__global__ void __launch_bounds__(256) softmax_rows(const __half* __restrict__ E,
                                                    bf16* __restrict__ P)
{
    const int tid = threadIdx.x;
    const int row = blockIdx.x;
    const int b   = blockIdx.y;
    const __half* p = E + ((size_t)b * NP + row) * NP;

    float v[8];
    float mx = -3.4e38f;
    #pragma unroll
    for (int k = 0; k < 8; k++) { v[k] = __half2float(p[tid + k*256]); mx = fmaxf(mx, v[k]); }

    #pragma unroll
    for (int o = 16; o > 0; o >>= 1) mx = fmaxf(mx, __shfl_xor_sync(0xffffffffu, mx, o));
    __shared__ float red[8];
    if ((tid & 31) == 0) red[tid >> 5] = mx;
    __syncthreads();
    mx = red[0];
    #pragma unroll
    for (int w = 1; w < 8; w++) mx = fmaxf(mx, red[w]);

    float s = 0.f;
    #pragma unroll
    for (int k = 0; k < 8; k++) { v[k] = __expf(v[k] - mx); s += v[k]; }
    #pragma unroll
    for (int o = 16; o > 0; o >>= 1) s += __shfl_xor_sync(0xffffffffu, s, o);
    __syncthreads();
    if ((tid & 31) == 0) red[tid >> 5] = s;
    __syncthreads();
    s = red[0];
    #pragma unroll
    for (int w = 1; w < 8; w++) s += red[w];

    const float inv = 1.f / s;
    bf16* po = P + ((size_t)b * NP + row) * NP;
    #pragma unroll
    for (int k = 0; k < 8; k++) {
        int n = tid + k * 256;
        po[n] = __float2bfloat16(v[k] * inv);
    }
}

// column sums of bf16 P: coalesced row-major reads, 8 partial atomics/address
__global__ void __launch_bounds__(256) colsum_kernel(const bf16* __restrict__ P,
                                                     float* __restrict__ d)
{
    const int b = blockIdx.z;
    const int m = blockIdx.x * 256 + threadIdx.x;
    const int n0 = blockIdx.y * (NP / 8);
    const bf16* pb = P + (size_t)b * NP * NP;
    float s = 0.f;
    #pragma unroll 4
    for (int n = n0; n < n0 + NP / 8; n++)
        s += __bfloat162float(pb[(size_t)n * NP + m]);
    atomicAdd(&d[b * NP + m], s);
}

__global__ void zero_d_kernel(float* d) { d[blockIdx.x * 256 + threadIdx.x] = 0.f; }

// inv_d = 1/(1e-9 + d), so XR epilogue multiplies instead of dividing
__global__ void rcp_d_kernel(const float* __restrict__ d, float* __restrict__ dinv)
{
    int i = blockIdx.x * 256 + threadIdx.x;
    dinv[i] = __frcp_rn(1e-9f + d[i]);
}

// ---------------- launch -----------------------------------------------------
extern "C" void kernel_launch(void* const* d_in, const int* in_sizes, int n_in,
                              void* d_out, int out_size)
{
    const float* x       = (const float*)d_in[0];
    const float* conv1_w = (const float*)d_in[1];
    const float* conv2_w = (const float*)d_in[2];
    const float* bn1_g = (const float*)d_in[3];
    const float* bn1_b = (const float*)d_in[4];
    const float* bn1_m = (const float*)d_in[5];
    const float* bn1_v = (const float*)d_in[6];
    const float* bn2_g = (const float*)d_in[7];
    const float* bn2_b = (const float*)d_in[8];
    const float* bn2_m = (const float*)d_in[9];
    const float* bn2_v = (const float*)d_in[10];
    const float* sa_qk_w = (const float*)d_in[11];
    const float* sa_v_w  = (const float*)d_in[12];
    const float* sa_v_b  = (const float*)d_in[13];
    const float* sa_t_w  = (const float*)d_in[14];
    const float* sa_t_b  = (const float*)d_in[15];
    const float* sa_g    = (const float*)d_in[16];
    const float* sa_b    = (const float*)d_in[17];
    const float* sa_m    = (const float*)d_in[18];
    const float* sa_var  = (const float*)d_in[19];
    float* out = (float*)d_out;

    float *h0, *h1, *dcol, *dinv, *bnp;
    __half* energy;
    bf16 *xB, *hB0, *hB1, *qbuf, *Pb, *xv, *uB, *wA;
    cudaGetSymbolAddress((void**)&h0,     g_h0);
    cudaGetSymbolAddress((void**)&h1,     g_h1);
    cudaGetSymbolAddress((void**)&energy, g_energy);
    cudaGetSymbolAddress((void**)&dcol,   g_d);
    cudaGetSymbolAddress((void**)&dinv,   g_dinv);
    cudaGetSymbolAddress((void**)&bnp,    g_bnp);
    cudaGetSymbolAddress((void**)&xB,     g_xB);
    cudaGetSymbolAddress((void**)&hB0,    g_hB0);
    cudaGetSymbolAddress((void**)&hB1,    g_hB1);
    cudaGetSymbolAddress((void**)&qbuf,   g_q);
    cudaGetSymbolAddress((void**)&Pb,     g_P);
    cudaGetSymbolAddress((void**)&xv,     g_xv);
    cudaGetSymbolAddress((void**)&uB,     g_uB);
    cudaGetSymbolAddress((void**)&wA,     g_wA);

    const size_t sB2 = (size_t)2 * C * NP;     // [hi;lo] B-form stride (512x2048)
    const size_t sQ2 = (size_t)2 * CQ * NP;    // q split stride (128x2048)
    const size_t sP  = (size_t)NP * NP;
    const size_t sHN = (size_t)C * NP;

    // opt in to >48KB dynamic smem (immediate driver calls; not graph-captured)
    cudaFuncSetAttribute(gemm_bf16<256, 2048, 768, 128, 128, false, M_CONV1, true, true>,
                         cudaFuncAttributeMaxDynamicSharedMemorySize, SMEM_BIG);
    cudaFuncSetAttribute(gemm_bf16<256, 2048, 768, 128, 128, false, M_CONV2, true, true>,
                         cudaFuncAttributeMaxDynamicSharedMemorySize, SMEM_BIG);
    cudaFuncSetAttribute(gemm_bf16<64, 2048, 768, 64, 128, false, M_Q, true, true>,
                         cudaFuncAttributeMaxDynamicSharedMemorySize, SMEM_Q);
    cudaFuncSetAttribute(gemm_bf16<2048, 2048, 192, 128, 128, true, M_ENERGY, true, true, true>,
                         cudaFuncAttributeMaxDynamicSharedMemorySize, SMEM_BIG);
    cudaFuncSetAttribute(gemm_bf16<256, 2048, 512, 128, 128, false, M_XV, false, false, false, true>,
                         cudaFuncAttributeMaxDynamicSharedMemorySize, SMEM_BIG);
    cudaFuncSetAttribute(gemm_bf16<256, 2048, 2048, 128, 128, false, M_XR, false, false>,
                         cudaFuncAttributeMaxDynamicSharedMemorySize, SMEM_BIG);
    cudaFuncSetAttribute(gemm_bf16<256, 2048, 768, 128, 128, false, M_TOUT, true, true>,
                         cudaFuncAttributeMaxDynamicSharedMemorySize, SMEM_BIG);

    bn_prep<<<6, 256>>>(bn1_g, bn1_b, bn1_m, bn1_v,
                        bn2_g, bn2_b, bn2_m, bn2_v,
                        sa_g, sa_b, sa_m, sa_var, sa_t_b);

    wsplit_all<<<2816, 256>>>(conv1_w, conv2_w, sa_qk_w, sa_v_w, sa_t_w);

    xsplitB<<<(BATCH * C * NP) / 256, 256>>>(x, xB);

    // conv1: split-only -> hB0
    gemm_bf16<256, 2048, 768, 128, 128, false, M_CONV1, true, true>
        <<<dim3(16, 2, BATCH), 256, SMEM_BIG>>>(wA + (size_t)0 * 512, 0, xB, sB2,
                                      nullptr, 0, bnp + 0, bnp + C, nullptr, nullptr,
                                      hB0, sB2);
    // conv2: fp32 h0 + split hB1
    gemm_bf16<256, 2048, 768, 128, 128, false, M_CONV2, true, true>
        <<<dim3(16, 2, BATCH), 256, SMEM_BIG>>>(wA + (size_t)256 * 512, 0, hB0, sB2,
                                      h0, sHN, bnp + 2*C, bnp + 3*C, nullptr, nullptr,
                                      hB1, sB2);

    float* hcur = h0;
    float* hnxt = h1;
    bf16* hBcur = hB1;
    bf16* hBnxt = hB0;
    for (int i = 0; i < 4; i++) {
        // q (split [hi;lo]) -> qbuf   (contract over C=256 -> K3=768)
        gemm_bf16<64, 2048, 768, 64, 128, false, M_Q, true, true>
            <<<dim3(16, 1, BATCH), 256, SMEM_Q>>>(wA + (size_t)(512 + i*64) * 512, 0,
                                          hBcur, sB2,
                                          nullptr, 0, nullptr, nullptr, nullptr, nullptr,
                                          qbuf, sQ2);
        // energy = q^T q, symmetric: only upper-triangle block pairs (136 of 256)
        gemm_bf16<2048, 2048, 192, 128, 128, true, M_ENERGY, true, true, true>
            <<<dim3(136, 1, BATCH), 256, SMEM_BIG>>>(qbuf, sQ2, qbuf, sQ2,
                                           (float*)energy, sP, nullptr, nullptr, nullptr,
                                           nullptr, nullptr, 0);
        // softmax (no atomics), then coalesced column-sum, then 1/d
        softmax_rows<<<dim3(NP, BATCH), 256>>>(energy, Pb);
        zero_d_kernel<<<BATCH * NP / 256, 256>>>(dcol);
        colsum_kernel<<<dim3(NP / 256, 8, BATCH), 256>>>(Pb, dcol);
        rcp_d_kernel<<<BATCH * NP / 256, 256>>>(dcol, dinv);
        // xv = v_w @ h + v_b -> plain bf16  (2-term split: K3=512, B reads [hi;hi])
        gemm_bf16<256, 2048, 512, 128, 128, false, M_XV, false, false, false, true>
            <<<dim3(16, 2, BATCH), 256, SMEM_BIG>>>(wA + (size_t)(768 + i*256) * 512, 0,
                                          hBcur, sB2,
                                          nullptr, 0, sa_v_b + (size_t)i * C, nullptr,
                                          nullptr, nullptr, xv, sHN);
        // u = h - (xv @ P)*inv_d -> uB split (pure bf16 GEMM, K=2048)
        gemm_bf16<256, 2048, 2048, 128, 128, false, M_XR, false, false>
            <<<dim3(16, 2, BATCH), 256, SMEM_BIG>>>(xv, sHN, Pb, sP,
                                          nullptr, 0, hcur, dinv, nullptr, nullptr,
                                          uB, sB2);
        // h_next = h + relu(bn(t_w @ u)); out slice + fp32 hnxt + split hBnxt
        gemm_bf16<256, 2048, 768, 128, 128, false, M_TOUT, true, true>
            <<<dim3(16, 2, BATCH), 256, SMEM_BIG>>>(wA + (size_t)(1792 + i*256) * 512, 0,
                                          uB, sB2,
                                          hnxt, sHN, bnp + (4+i)*C, bnp + (8+i)*C, hcur,
                                          out + (size_t)i * C * NP,
                                          hBnxt, sB2);
        float* tf = hcur; hcur = hnxt; hnxt = tf;
        bf16* tb = hBcur; hBcur = hBnxt; hBnxt = tb;
    }
    (void)in_sizes; (void)n_in; (void)out_size;
}

// round 16
// speedup vs baseline: 1.5418x; 1.0875x over previous
#include <cuda_runtime.h>
#include <cuda_bf16.h>
#include <cuda_fp16.h>
#include <cstdint>
#include <cstddef>

using bf16 = __nv_bfloat16;

constexpr int BATCH = 16;
constexpr int C     = 256;
constexpr int NP    = 2048;
constexpr int CQ    = 64;
constexpr float EPSBN = 1e-3f;

// ---------------- scratch (static device buffers; no allocation) -------------
__device__ float  g_h0[BATCH * C * NP];
__device__ float  g_h1[BATCH * C * NP];
__device__ __half g_energy[(size_t)BATCH * NP * NP];            // 134 MB
__device__ bf16   g_P     [(size_t)BATCH * NP * NP];            // 134 MB
__device__ bf16   g_xB [(size_t)BATCH * 2 * C * NP];            // [hi;lo]
__device__ bf16   g_hB0[(size_t)BATCH * 2 * C * NP];
__device__ bf16   g_hB1[(size_t)BATCH * 2 * C * NP];
__device__ bf16   g_q  [(size_t)BATCH * 2 * CQ * NP];           // [hi;lo]
__device__ bf16   g_xv [(size_t)BATCH * C * NP];                // plain bf16
__device__ bf16   g_uB [(size_t)BATCH * 2 * C * NP];
__device__ float  g_d  [BATCH * NP];
__device__ float  g_dinv[BATCH * NP];
__device__ float  g_bnp[12 * C];
// weight splits [hi(256)|lo(256)]: rows: conv1 0..255, conv2 256..511, qk 512..767,
// v 768..1791, t 1792..2815
__device__ bf16   g_wA [(size_t)2816 * 512];

// ---------------- BN prefold -------------------------------------------------
__global__ void bn_prep(const float* g1, const float* b1, const float* m1, const float* v1,
                        const float* g2, const float* b2, const float* m2, const float* v2,
                        const float* sg, const float* sb, const float* sm, const float* sv,
                        const float* stb)
{
    int c = threadIdx.x;
    int w = blockIdx.x;
    if (w == 0) {
        float a = g1[c] * rsqrtf(v1[c] + EPSBN);
        g_bnp[c] = a; g_bnp[C + c] = b1[c] - m1[c] * a;
    } else if (w == 1) {
        float a = g2[c] * rsqrtf(v2[c] + EPSBN);
        g_bnp[2*C + c] = a; g_bnp[3*C + c] = b2[c] - m2[c] * a;
    } else {
        int i = w - 2;
        float a = sg[i*C + c] * rsqrtf(sv[i*C + c] + EPSBN);
        g_bnp[(4+i)*C + c] = a;
        g_bnp[(8+i)*C + c] = sb[i*C + c] - sm[i*C + c] * a + a * stb[i*C + c];
    }
}

// ---------------- split helpers ---------------------------------------------
__device__ __forceinline__ void split2(float v, bf16& hi, bf16& lo)
{
    hi = __float2bfloat16(v);
    lo = __float2bfloat16(v - __bfloat162float(hi));
}

// ALL weights in one launch: rows 0..255 conv1, 256..511 conv2, 512..767 qk,
// 768..1791 v, 1792..2815 t.
__global__ void wsplit_all(const float* __restrict__ c1, const float* __restrict__ c2,
                           const float* __restrict__ qk, const float* __restrict__ vw,
                           const float* __restrict__ tw)
{
    int idx = blockIdx.x * 256 + threadIdx.x;   // 0 .. 2816*256-1
    int row = idx >> 8, k = idx & 255;
    const float* src;
    int r;
    if (row < 256)       { src = c1; r = row; }
    else if (row < 512)  { src = c2; r = row - 256; }
    else if (row < 768)  { src = qk; r = row - 512; }
    else if (row < 1792) { src = vw; r = row - 768; }
    else                 { src = tw; r = row - 1792; }
    bf16 hi, lo; split2(src[r * 256 + k], hi, lo);
    bf16* d = g_wA + (size_t)row * 512;
    d[k] = hi; d[256 + k] = lo;
}

// x: src fp32 [B,C,NP] -> dst bf16 [B,2C,NP] = [hi;lo]
__global__ void xsplitB(const float* __restrict__ src, bf16* __restrict__ dst)
{
    size_t idx = (size_t)blockIdx.x * 256 + threadIdx.x;
    int b = (int)(idx / ((size_t)C * NP));
    size_t rem = idx - (size_t)b * C * NP;
    bf16 hi, lo; split2(src[idx], hi, lo);
    bf16* d = dst + (size_t)b * 2 * C * NP;
    d[rem] = hi; d[(size_t)C * NP + rem] = lo;
}

// ---------------- mma.sync bf16 GEMM with fused epilogues --------------------
enum { M_CONV1 = 0, M_CONV2, M_Q, M_ENERGY, M_XV, M_XR, M_TOUT };

__device__ __forceinline__ void ldm_x4(uint32_t* r, uint32_t a)
{
    asm volatile("ldmatrix.sync.aligned.m8n8.x4.shared.b16 {%0,%1,%2,%3}, [%4];"
                 : "=r"(r[0]), "=r"(r[1]), "=r"(r[2]), "=r"(r[3]) : "r"(a));
}
__device__ __forceinline__ void ldm_x4_t(uint32_t* r, uint32_t a)
{
    asm volatile("ldmatrix.sync.aligned.m8n8.x4.trans.shared.b16 {%0,%1,%2,%3}, [%4];"
                 : "=r"(r[0]), "=r"(r[1]), "=r"(r[2]), "=r"(r[3]) : "r"(a));
}
__device__ __forceinline__ void cpa16(uint32_t s, const void* g)
{
    asm volatile("cp.async.cg.shared.global [%0], [%1], 16;" :: "r"(s), "l"(g));
}
__device__ __forceinline__ void mma_bf16(float* c, const uint32_t* a, const uint32_t* b)
{
    asm volatile("mma.sync.aligned.m16n8k16.row.col.f32.bf16.bf16.f32 "
                 "{%0,%1,%2,%3}, {%4,%5,%6,%7}, {%8,%9}, {%0,%1,%2,%3};"
                 : "+f"(c[0]), "+f"(c[1]), "+f"(c[2]), "+f"(c[3])
                 : "r"(a[0]), "r"(a[1]), "r"(a[2]), "r"(a[3]), "r"(b[0]), "r"(b[1]));
}

// MAPA:  A logical k-thirds [hi|lo|hi] stored [hi|lo]  (phys K = 2*K3/3)
// MAPB:  B logical k-thirds [hi;hi;lo] stored [hi;lo]
// MAPBH: B logical k-halves [hi;hi]    stored [hi;lo]  (2-term split: XV)
// SYM:   symmetric NxN product (energy); off-diagonal tiles mirrored via smem.
// BK=64, 2-stage, wait_group 0 — validated optimum.
template<int M, int N, int K3, int BM, int BN, bool ATRANS, int MODE,
         bool MAPA, bool MAPB, bool SYM = false, bool MAPBH = false>
__global__ void __launch_bounds__(256, 2)
gemm_bf16(const bf16* __restrict__ A, size_t sA,
          const bf16* __restrict__ B, size_t sB,
          float* __restrict__ Cp, size_t sC,
          const float* __restrict__ e1, const float* __restrict__ e2,
          const float* __restrict__ e3, float* __restrict__ out2,
          bf16* __restrict__ sp1, size_t sSp1)
{
    constexpr int BK = 64;
    constexpr int KB = K3 / BK;
    constexpr int T3 = K3 / 3;
    constexpr int WM = BM / 2, WN = BN / 4;
    constexpr int MT = WM / 16, NT = WN / 8;
    constexpr int A_STAGE = BM * BK * 2;      // bytes
    constexpr int B_STAGE = BK * BN * 2;
    constexpr int STAGE   = A_STAGE + B_STAGE;
    constexpr int CPRA = BK / 8;              // 16B chunks per A row (non-trans)
    constexpr int LDA = ATRANS ? M : (MAPA ? 2 * T3 : K3);

    extern __shared__ __align__(16) uint8_t smem[];
    const uint32_t s0 = (uint32_t)__cvta_generic_to_shared(smem);

    const int tid  = threadIdx.x;
    const int lane = tid & 31;
    const int w    = tid >> 5;
    const int wm   = w >> 2, wn = w & 3;
    const int b    = blockIdx.z;

    int bxv = 0, byv = 0, m0, n0;
    if (SYM) {
        int t = blockIdx.x;
        bxv = (int)floorf((sqrtf(8.0f * t + 1.0f) - 1.0f) * 0.5f);
        while ((bxv + 1) * (bxv + 2) / 2 <= t) ++bxv;
        while (bxv * (bxv + 1) / 2 > t) --bxv;
        byv = t - bxv * (bxv + 1) / 2;
        m0 = byv * BM;
        n0 = bxv * BN;
    } else {
        m0 = blockIdx.y * BM;
        n0 = blockIdx.x * BN;
    }

    const bf16* Ab = A + (size_t)b * sA;
    const bf16* Bb = B + (size_t)b * sB;

    float acc[MT][NT][4];
    #pragma unroll
    for (int i = 0; i < MT; i++)
        #pragma unroll
        for (int j = 0; j < NT; j++)
            #pragma unroll
            for (int q = 0; q < 4; q++) acc[i][j][q] = 0.f;

    auto issue = [&](int kb, int stage) {
        const int k0 = kb * BK;
        const int k0A = MAPA ? (k0 < 2 * T3 ? k0 : k0 - 2 * T3) : k0;
        const int k0B = MAPBH ? (k0 < K3 / 2 ? k0 : k0 - K3 / 2)
                              : (MAPB ? (k0 < T3 ? k0 : k0 - T3) : k0);
        const uint32_t sAst = s0 + stage * STAGE;
        const uint32_t sBst = sAst + A_STAGE;
        if (ATRANS) {
            constexpr int CH = BK * BM / 8;   // 16B chunks
            #pragma unroll
            for (int i = 0; i < CH / 256; i++) {
                int c = tid + i * 256;
                int r = c / (BM / 8), ch = c % (BM / 8);
                const bf16* g = Ab + (size_t)(k0A + r) * LDA + m0 + ch * 8;
                uint32_t s = sAst + r * (BM * 2) + ((ch ^ (r & 7)) << 4);
                cpa16(s, g);
            }
        } else {
            constexpr int CH = BM * BK / 8;
            #pragma unroll
            for (int i = 0; i < CH / 256; i++) {
                int c = tid + i * 256;
                int r = c / CPRA, ch = c % CPRA;
                const bf16* g = Ab + (size_t)(m0 + r) * LDA + k0A + ch * 8;
                uint32_t s = sAst + r * (BK * 2) + ((ch ^ (r & (CPRA - 1))) << 4);
                cpa16(s, g);
            }
        }
        {
            constexpr int CH = BK * BN / 8;
            #pragma unroll
            for (int i = 0; i < CH / 256; i++) {
                int c = tid + i * 256;
                int r = c / (BN / 8), ch = c % (BN / 8);
                const bf16* g = Bb + (size_t)(k0B + r) * N + n0 + ch * 8;
                uint32_t s = sBst + r * (BN * 2) + ((ch ^ (r & 7)) << 4);
                cpa16(s, g);
            }
        }
        asm volatile("cp.async.commit_group;");
    };

    auto compute = [&](int stage) {
        const uint32_t sAst = s0 + stage * STAGE;
        const uint32_t sBst = sAst + A_STAGE;
        #pragma unroll
        for (int ks = 0; ks < BK / 16; ks++) {
            uint32_t afr[MT][4];
            uint32_t bfr[NT][2];
            #pragma unroll
            for (int mt = 0; mt < MT; mt++) {
                if (!ATRANS) {
                    int r  = wm * WM + mt * 16 + (lane & 15);
                    int ch = 2 * ks + (lane >> 4);
                    uint32_t a = sAst + r * (BK * 2) + ((ch ^ (r & (CPRA - 1))) << 4);
                    ldm_x4(afr[mt], a);
                } else {
                    int k  = 16 * ks + (lane & 7) + ((lane >> 4) << 3);
                    int mo = wm * WM + mt * 16 + (((lane >> 3) & 1) << 3);
                    int ch = mo >> 3;
                    uint32_t a = sAst + k * (BM * 2) + ((ch ^ (k & 7)) << 4);
                    ldm_x4_t(afr[mt], a);
                }
            }
            #pragma unroll
            for (int p = 0; p < NT / 2; p++) {
                int k  = 16 * ks + (lane & 15);
                int ch = (wn * WN + p * 16) / 8 + (lane >> 4);
                uint32_t a = sBst + k * (BN * 2) + ((ch ^ (k & 7)) << 4);
                uint32_t r4[4];
                ldm_x4_t(r4, a);
                bfr[2*p][0] = r4[0]; bfr[2*p][1] = r4[1];
                bfr[2*p+1][0] = r4[2]; bfr[2*p+1][1] = r4[3];
            }
            #pragma unroll
            for (int mt = 0; mt < MT; mt++)
                #pragma unroll
                for (int nt = 0; nt < NT; nt++)
                    mma_bf16(acc[mt][nt], afr[mt], bfr[nt]);
        }
    };

    issue(0, 0);
    for (int kb = 0; kb < KB; kb++) {
        asm volatile("cp.async.wait_group 0;");
        __syncthreads();
        if (kb + 1 < KB) issue(kb + 1, (kb + 1) & 1);
        compute(kb & 1);
    }

    // ----------------------- epilogue -----------------------
    float*  Cb  = (MODE == M_CONV2 || MODE == M_TOUT) ? Cp + (size_t)b * sC : nullptr;
    __half* CbH = (MODE == M_ENERGY) ? (__half*)Cp + (size_t)b * sC : nullptr;
    const int er = lane >> 2;
    const int ec = (lane & 3) * 2;

    const bool mirror = SYM && (bxv != byv);
    __half* st = reinterpret_cast<__half*>(smem);   // 128x(128+2) tile
    if (mirror) __syncthreads();   // stages done; reuse smem for transpose

    #pragma unroll
    for (int mt = 0; mt < MT; mt++) {
        #pragma unroll
        for (int half = 0; half < 2; half++) {
            const int lm = wm * WM + mt * 16 + er + half * 8;
            const int gm = m0 + lm;
            float alpha = 0.f, beta = 0.f;
            if (MODE == M_CONV1 || MODE == M_CONV2 || MODE == M_TOUT) {
                alpha = e1[gm]; beta = e2[gm];
            } else if (MODE == M_XV) {
                alpha = e1[gm];
            }
            #pragma unroll
            for (int nt = 0; nt < NT; nt++) {
                const int ln = wn * WN + nt * 8 + ec;
                const int gn = n0 + ln;
                float s0v = acc[mt][nt][half * 2 + 0];
                float s1v = acc[mt][nt][half * 2 + 1];
                float r0, r1;

                if (MODE == M_CONV1 || MODE == M_CONV2) {
                    r0 = fmaxf(fmaf(alpha, s0v, beta), 0.f);
                    r1 = fmaxf(fmaf(alpha, s1v, beta), 0.f);
                } else if (MODE == M_Q || MODE == M_ENERGY) {
                    r0 = s0v; r1 = s1v;
                } else if (MODE == M_XV) {
                    r0 = s0v + alpha; r1 = s1v + alpha;
                } else if (MODE == M_XR) {
                    // e2 = precomputed 1/(1e-9+d): multiply instead of divide
                    float i0 = e2[(size_t)b * NP + gn];
                    float i1 = e2[(size_t)b * NP + gn + 1];
                    float h0 = e1[(size_t)b * M * N + (size_t)gm * N + gn];
                    float h1 = e1[(size_t)b * M * N + (size_t)gm * N + gn + 1];
                    r0 = fmaf(-s0v, i0, h0);
                    r1 = fmaf(-s1v, i1, h1);
                } else { // M_TOUT
                    float t0 = fmaxf(fmaf(alpha, s0v, beta), 0.f);
                    float t1 = fmaxf(fmaf(alpha, s1v, beta), 0.f);
                    r0 = e3[(size_t)b * M * N + (size_t)gm * N + gn] + t0;
                    r1 = e3[(size_t)b * M * N + (size_t)gm * N + gn + 1] + t1;
                }

                if (MODE == M_ENERGY) {
                    __half2 hv = __floats2half2_rn(r0, r1);
                    *(__half2*)&CbH[(size_t)gm * N + gn] = hv;
                    if (mirror) {
                        st[lm * (BN + 2) + ln]     = __low2half(hv);
                        st[lm * (BN + 2) + ln + 1] = __high2half(hv);
                    }
                }
                if (MODE == M_CONV2 || MODE == M_TOUT) {
                    float2 v; v.x = r0; v.y = r1;
                    *(float2*)&Cb[(size_t)gm * N + gn] = v;
                }
                if (MODE == M_TOUT) {
                    float2 v; v.x = r0; v.y = r1;
                    *(float2*)&out2[(size_t)b * 4 * M * N + (size_t)gm * N + gn] = v;
                }

                if (MODE == M_XV) {
                    __nv_bfloat162 hh;
                    hh.x = __float2bfloat16(r0); hh.y = __float2bfloat16(r1);
                    bf16* d = sp1 + (size_t)b * sSp1;
                    *(__nv_bfloat162*)&d[(size_t)gm * N + gn] = hh;
                } else if (MODE == M_CONV1 || MODE == M_CONV2 ||
                           MODE == M_XR || MODE == M_TOUT || MODE == M_Q) {
                    // canonical split [hi;lo]
                    bf16 h0b, l0b, h1b, l1b;
                    split2(r0, h0b, l0b); split2(r1, h1b, l1b);
                    __nv_bfloat162 hh; hh.x = h0b; hh.y = h1b;
                    __nv_bfloat162 ll; ll.x = l0b; ll.y = l1b;
                    bf16* d = sp1 + (size_t)b * sSp1;
                    *(__nv_bfloat162*)&d[(size_t)gm * N + gn] = hh;
                    *(__nv_bfloat162*)&d[(size_t)(M + gm) * N + gn] = ll;
                }
            }
        }
    }

    if (MODE == M_ENERGY && mirror) {
        __syncthreads();
        // write transposed tile: rows [n0, n0+BN), cols [m0, m0+BM)
        #pragma unroll
        for (int pass = 0; pass < (BM * BN) / (256 * 8); pass++) {
            int idx = pass * 256 + tid;
            int j = idx >> 4;            // transposed row 0..127
            int cchunk = (idx & 15) * 8; // col chunk
            __half tmp[8];
            #pragma unroll
            for (int k = 0; k < 8; k++) tmp[k] = st[(cchunk + k) * (BN + 2) + j];
            *(uint4*)&CbH[(size_t)(n0 + j) * N + m0 + cchunk] = *(uint4*)tmp;
        }
    }
}

// smem sizes (BK=64, 2 stages)
constexpr int SMEM_BIG = 2 * (128 * 64 * 2 + 64 * 128 * 2);   // 64 KB
constexpr int SMEM_Q   = 2 * (64 * 64 * 2 + 64 * 128 * 2);    // 48 KB

// ---- softmax over 8 rows per block, fused column-sum in REGISTERS (R15) -----
// Thread owns columns {tid + k*256} for all 8 rows -> accumulates d partials in
// registers; ONE atomicAdd per column per block (8.4M atomics/layer vs 67M,
// 256-way same-address conflicts). Replaces the separate colsum pass entirely.
constexpr int SM_ROWS = 8;
__global__ void __launch_bounds__(256) softmax_rows(const __half* __restrict__ E,
                                                    bf16* __restrict__ P,
                                                    float* __restrict__ dcol)
{
    const int tid  = threadIdx.x;
    const int row0 = blockIdx.x * SM_ROWS;
    const int b    = blockIdx.y;
    __shared__ float red[8];

    float dacc[8];
    #pragma unroll
    for (int k = 0; k < 8; k++) dacc[k] = 0.f;

    for (int rr = 0; rr < SM_ROWS; rr++) {
        const __half* p = E + ((size_t)b * NP + row0 + rr) * NP;
        float v[8];
        float mx = -3.4e38f;
        #pragma unroll
        for (int k = 0; k < 8; k++) {
            v[k] = __half2float(p[tid + k*256]);
            mx = fmaxf(mx, v[k]);
        }
        #pragma unroll
        for (int o = 16; o > 0; o >>= 1) mx = fmaxf(mx, __shfl_xor_sync(0xffffffffu, mx, o));
        if ((tid & 31) == 0) red[tid >> 5] = mx;
        __syncthreads();
        mx = red[0];
        #pragma unroll
        for (int w = 1; w < 8; w++) mx = fmaxf(mx, red[w]);

        float s = 0.f;
        #pragma unroll
        for (int k = 0; k < 8; k++) { v[k] = __expf(v[k] - mx); s += v[k]; }
        #pragma unroll
        for (int o = 16; o > 0; o >>= 1) s += __shfl_xor_sync(0xffffffffu, s, o);
        __syncthreads();
        if ((tid & 31) == 0) red[tid >> 5] = s;
        __syncthreads();
        s = red[0];
        #pragma unroll
        for (int w = 1; w < 8; w++) s += red[w];

        const float inv = 1.f / s;
        bf16* po = P + ((size_t)b * NP + row0 + rr) * NP;
        #pragma unroll
        for (int k = 0; k < 8; k++) {
            bf16 pb = __float2bfloat16(v[k] * inv);
            po[tid + k*256] = pb;
            dacc[k] += __bfloat162float(pb);
        }
        __syncthreads();   // red[] reused next row
    }

    float* dc = dcol + (size_t)b * NP;
    #pragma unroll
    for (int k = 0; k < 8; k++) atomicAdd(&dc[tid + k*256], dacc[k]);
}

__global__ void zero_d_kernel(float* d) { d[blockIdx.x * 256 + threadIdx.x] = 0.f; }

// inv_d = 1/(1e-9 + d), so XR epilogue multiplies instead of dividing
__global__ void rcp_d_kernel(const float* __restrict__ d, float* __restrict__ dinv)
{
    int i = blockIdx.x * 256 + threadIdx.x;
    dinv[i] = __frcp_rn(1e-9f + d[i]);
}

// ---------------- launch -----------------------------------------------------
extern "C" void kernel_launch(void* const* d_in, const int* in_sizes, int n_in,
                              void* d_out, int out_size)
{
    const float* x       = (const float*)d_in[0];
    const float* conv1_w = (const float*)d_in[1];
    const float* conv2_w = (const float*)d_in[2];
    const float* bn1_g = (const float*)d_in[3];
    const float* bn1_b = (const float*)d_in[4];
    const float* bn1_m = (const float*)d_in[5];
    const float* bn1_v = (const float*)d_in[6];
    const float* bn2_g = (const float*)d_in[7];
    const float* bn2_b = (const float*)d_in[8];
    const float* bn2_m = (const float*)d_in[9];
    const float* bn2_v = (const float*)d_in[10];
    const float* sa_qk_w = (const float*)d_in[11];
    const float* sa_v_w  = (const float*)d_in[12];
    const float* sa_v_b  = (const float*)d_in[13];
    const float* sa_t_w  = (const float*)d_in[14];
    const float* sa_t_b  = (const float*)d_in[15];
    const float* sa_g    = (const float*)d_in[16];
    const float* sa_b    = (const float*)d_in[17];
    const float* sa_m    = (const float*)d_in[18];
    const float* sa_var  = (const float*)d_in[19];
    float* out = (float*)d_out;

    float *h0, *h1, *dcol, *dinv, *bnp;
    __half* energy;
    bf16 *xB, *hB0, *hB1, *qbuf, *Pb, *xv, *uB, *wA;
    cudaGetSymbolAddress((void**)&h0,     g_h0);
    cudaGetSymbolAddress((void**)&h1,     g_h1);
    cudaGetSymbolAddress((void**)&energy, g_energy);
    cudaGetSymbolAddress((void**)&dcol,   g_d);
    cudaGetSymbolAddress((void**)&dinv,   g_dinv);
    cudaGetSymbolAddress((void**)&bnp,    g_bnp);
    cudaGetSymbolAddress((void**)&xB,     g_xB);
    cudaGetSymbolAddress((void**)&hB0,    g_hB0);
    cudaGetSymbolAddress((void**)&hB1,    g_hB1);
    cudaGetSymbolAddress((void**)&qbuf,   g_q);
    cudaGetSymbolAddress((void**)&Pb,     g_P);
    cudaGetSymbolAddress((void**)&xv,     g_xv);
    cudaGetSymbolAddress((void**)&uB,     g_uB);
    cudaGetSymbolAddress((void**)&wA,     g_wA);

    const size_t sB2 = (size_t)2 * C * NP;     // [hi;lo] B-form stride (512x2048)
    const size_t sQ2 = (size_t)2 * CQ * NP;    // q split stride (128x2048)
    const size_t sP  = (size_t)NP * NP;
    const size_t sHN = (size_t)C * NP;

    // opt in to >48KB dynamic smem (immediate driver calls; not graph-captured)
    cudaFuncSetAttribute(gemm_bf16<256, 2048, 768, 128, 128, false, M_CONV1, true, true>,
                         cudaFuncAttributeMaxDynamicSharedMemorySize, SMEM_BIG);
    cudaFuncSetAttribute(gemm_bf16<256, 2048, 768, 128, 128, false, M_CONV2, true, true>,
                         cudaFuncAttributeMaxDynamicSharedMemorySize, SMEM_BIG);
    cudaFuncSetAttribute(gemm_bf16<64, 2048, 768, 64, 128, false, M_Q, true, true>,
                         cudaFuncAttributeMaxDynamicSharedMemorySize, SMEM_Q);
    cudaFuncSetAttribute(gemm_bf16<2048, 2048, 192, 128, 128, true, M_ENERGY, true, true, true>,
                         cudaFuncAttributeMaxDynamicSharedMemorySize, SMEM_BIG);
    cudaFuncSetAttribute(gemm_bf16<256, 2048, 512, 128, 128, false, M_XV, false, false, false, true>,
                         cudaFuncAttributeMaxDynamicSharedMemorySize, SMEM_BIG);
    cudaFuncSetAttribute(gemm_bf16<256, 2048, 2048, 128, 128, false, M_XR, false, false>,
                         cudaFuncAttributeMaxDynamicSharedMemorySize, SMEM_BIG);
    cudaFuncSetAttribute(gemm_bf16<256, 2048, 768, 128, 128, false, M_TOUT, true, true>,
                         cudaFuncAttributeMaxDynamicSharedMemorySize, SMEM_BIG);

    bn_prep<<<6, 256>>>(bn1_g, bn1_b, bn1_m, bn1_v,
                        bn2_g, bn2_b, bn2_m, bn2_v,
                        sa_g, sa_b, sa_m, sa_var, sa_t_b);

    wsplit_all<<<2816, 256>>>(conv1_w, conv2_w, sa_qk_w, sa_v_w, sa_t_w);

    xsplitB<<<(BATCH * C * NP) / 256, 256>>>(x, xB);

    // conv1: split-only -> hB0
    gemm_bf16<256, 2048, 768, 128, 128, false, M_CONV1, true, true>
        <<<dim3(16, 2, BATCH), 256, SMEM_BIG>>>(wA + (size_t)0 * 512, 0, xB, sB2,
                                      nullptr, 0, bnp + 0, bnp + C, nullptr, nullptr,
                                      hB0, sB2);
    // conv2: fp32 h0 + split hB1
    gemm_bf16<256, 2048, 768, 128, 128, false, M_CONV2, true, true>
        <<<dim3(16, 2, BATCH), 256, SMEM_BIG>>>(wA + (size_t)256 * 512, 0, hB0, sB2,
                                      h0, sHN, bnp + 2*C, bnp + 3*C, nullptr, nullptr,
                                      hB1, sB2);

    float* hcur = h0;
    float* hnxt = h1;
    bf16* hBcur = hB1;
    bf16* hBnxt = hB0;
    for (int i = 0; i < 4; i++) {
        // q (split [hi;lo]) -> qbuf   (contract over C=256 -> K3=768)
        gemm_bf16<64, 2048, 768, 64, 128, false, M_Q, true, true>
            <<<dim3(16, 1, BATCH), 256, SMEM_Q>>>(wA + (size_t)(512 + i*64) * 512, 0,
                                          hBcur, sB2,
                                          nullptr, 0, nullptr, nullptr, nullptr, nullptr,
                                          qbuf, sQ2);
        // energy = q^T q, symmetric: only upper-triangle block pairs (136 of 256)
        gemm_bf16<2048, 2048, 192, 128, 128, true, M_ENERGY, true, true, true>
            <<<dim3(136, 1, BATCH), 256, SMEM_BIG>>>(qbuf, sQ2, qbuf, sQ2,
                                           (float*)energy, sP, nullptr, nullptr, nullptr,
                                           nullptr, nullptr, 0);
        // softmax with register-fused column-sum (8 rows/block), then 1/d
        zero_d_kernel<<<BATCH * NP / 256, 256>>>(dcol);
        softmax_rows<<<dim3(NP / SM_ROWS, BATCH), 256>>>(energy, Pb, dcol);
        rcp_d_kernel<<<BATCH * NP / 256, 256>>>(dcol, dinv);
        // xv = v_w @ h + v_b -> plain bf16  (2-term split: K3=512, B reads [hi;hi])
        gemm_bf16<256, 2048, 512, 128, 128, false, M_XV, false, false, false, true>
            <<<dim3(16, 2, BATCH), 256, SMEM_BIG>>>(wA + (size_t)(768 + i*256) * 512, 0,
                                          hBcur, sB2,
                                          nullptr, 0, sa_v_b + (size_t)i * C, nullptr,
                                          nullptr, nullptr, xv, sHN);
        // u = h - (xv @ P)*inv_d -> uB split (pure bf16 GEMM, K=2048)
        gemm_bf16<256, 2048, 2048, 128, 128, false, M_XR, false, false>
            <<<dim3(16, 2, BATCH), 256, SMEM_BIG>>>(xv, sHN, Pb, sP,
                                          nullptr, 0, hcur, dinv, nullptr, nullptr,
                                          uB, sB2);
        // h_next = h + relu(bn(t_w @ u)); out slice + fp32 hnxt + split hBnxt
        gemm_bf16<256, 2048, 768, 128, 128, false, M_TOUT, true, true>
            <<<dim3(16, 2, BATCH), 256, SMEM_BIG>>>(wA + (size_t)(1792 + i*256) * 512, 0,
                                          uB, sB2,
                                          hnxt, sHN, bnp + (4+i)*C, bnp + (8+i)*C, hcur,
                                          out + (size_t)i * C * NP,
                                          hBnxt, sB2);
        float* tf = hcur; hcur = hnxt; hnxt = tf;
        bf16* tb = hBcur; hBcur = hBnxt; hBnxt = tb;
    }
    (void)in_sizes; (void)n_in; (void)out_size;
}